// round 13
// baseline (speedup 1.0000x reference)
#include <cuda_runtime.h>
#include <cuda_bf16.h>
#include <cstdint>

// DeltaNet chunkwise delta-rule linear attention with decay.
// Round 13: scan = round-6 (best, 785-789us x4). Pre redesigned for 3 CTAs/SM:
//   smem 71KB (no ksT), f32x2 Gram, T-apply split into two passes so no
//   64-register arrays -> fits the 85-reg cap from __launch_bounds__(256,3).

#define BHn 16
#define LSEQ 4096
#define DK 256
#define DV 256
#define CC 32
#define NCH 128
#define CHELEM (CC*DK)

__device__ float g_wq[BHn*NCH*2*CHELEM];   // [bh][ch][k][64] {w2c,w2c+1,q2c,q2c+1}
__device__ float g_kn[BHn*NCH*CHELEM];     // [bh][ch][c][k]
__device__ float g_u [BHn*8*NCH*CC*32];    // [bh][vblk][ch][c][32]
__device__ float g_attn[BHn*NCH*CC*CC];    // [bh][ch][c][d], zero d>c
__device__ float g_gm[BHn*NCH];

typedef unsigned long long ull;
__device__ __forceinline__ void ffma2(ull &d, ull a, ull b) {
    asm("fma.rn.f32x2 %0, %1, %2, %0;" : "+l"(d) : "l"(a), "l"(b));
}
__device__ __forceinline__ void fadd2(ull &d, ull a) {
    asm("add.rn.f32x2 %0, %0, %1;" : "+l"(d) : "l"(a));
}
__device__ __forceinline__ ull pk2(float a, float b) {
    ull r; asm("mov.b64 %0, {%1, %2};" : "=l"(r) : "f"(a), "f"(b)); return r;
}
__device__ __forceinline__ float2 up2(ull p) {
    float2 r; asm("mov.b64 {%0, %1}, %2;" : "=f"(r.x), "=f"(r.y) : "l"(p)); return r;
}
__device__ __forceinline__ uint32_t smem_u32(const void* p) {
    uint32_t a;
    asm("{ .reg .u64 t; cvta.to.shared.u64 t, %1; cvt.u32.u64 %0, t; }" : "=r"(a) : "l"(p));
    return a;
}
__device__ __forceinline__ void bulkcp(uint32_t dst, const void* src, uint32_t bytes, uint32_t mbar) {
    asm volatile("cp.async.bulk.shared::cluster.global.mbarrier::complete_tx::bytes [%0], [%1], %2, [%3];"
                 :: "r"(dst), "l"(src), "r"(bytes), "r"(mbar) : "memory");
}
__device__ __forceinline__ void mbar_init(uint32_t mbar, uint32_t cnt) {
    asm volatile("mbarrier.init.shared.b64 [%0], %1;" :: "r"(mbar), "r"(cnt) : "memory");
}
__device__ __forceinline__ void mbar_expect(uint32_t mbar, uint32_t bytes) {
    asm volatile("mbarrier.arrive.expect_tx.shared.b64 _, [%0], %1;" :: "r"(mbar), "r"(bytes) : "memory");
}
__device__ __forceinline__ void mbar_wait(uint32_t mbar, uint32_t parity) {
    uint32_t done;
    asm volatile("{\n\t.reg .pred p;\n\t"
        "mbarrier.try_wait.parity.acquire.cta.shared::cta.b64 p, [%1], %2;\n\t"
        "selp.b32 %0, 1, 0, p;\n\t}" : "=r"(done) : "r"(mbar), "r"(parity) : "memory");
    if (!done) {
        asm volatile("{\n\t.reg .pred P1;\n\t"
            "WL_%=:\n\t"
            "mbarrier.try_wait.parity.acquire.cta.shared::cta.b64 P1, [%0], %1, 0x989680;\n\t"
            "@P1 bra.uni WD_%=;\n\t"
            "bra.uni WL_%=;\n\t"
            "WD_%=:\n\t}" :: "r"(mbar), "r"(parity) : "memory");
    }
}

// ================= pre (3 CTAs/SM: 71KB smem, <=85 regs) =================
#define PRE_SMEM_FLOATS (8320+8320+1056+32+32)

__global__ __launch_bounds__(256, 3)
void pre_kernel(const float* __restrict__ q, const float* __restrict__ k,
                const float* __restrict__ v, const float* __restrict__ beta,
                const float* __restrict__ gamma) {
    extern __shared__ float sm[];
    float* qs = sm; float* ks = sm + 8320; float* As = sm + 16640;
    float* bs = sm + 17696; float* gs = sm + 17728;

    const int tid = threadIdx.x, lane = tid & 31, wid = tid >> 5;
    const int bh = blockIdx.x >> 7, ch = blockIdx.x & 127;
    const long tok0 = (long)bh*LSEQ + (long)ch*CC;
    const float* qg = q + tok0*DK;
    const float* kg = k + tok0*DK;

    #pragma unroll 8
    for (int i = 0; i < 32; i++) {
        qs[i*260+tid] = qg[i*DK+tid];
        ks[i*260+tid] = kg[i*DK+tid];
    }
    if (tid < 32) { bs[tid] = beta[tok0+tid]; gs[tid] = gamma[tok0+tid]; }
    __syncthreads();

    // l2 normalize rows (warp per row)
    for (int r = wid; r < 32; r += 8) {
        float s = 0.f;
        #pragma unroll
        for (int x = lane; x < 256; x += 32) { float t = qs[r*260+x]; s += t*t; }
        for (int o = 16; o; o >>= 1) s += __shfl_xor_sync(~0u, s, o);
        float inv = rsqrtf(s + 1e-6f);
        #pragma unroll
        for (int x = lane; x < 256; x += 32) qs[r*260+x] *= inv;
        float s2 = 0.f;
        #pragma unroll
        for (int x = lane; x < 256; x += 32) { float t = ks[r*260+x]; s2 += t*t; }
        for (int o = 16; o; o >>= 1) s2 += __shfl_xor_sync(~0u, s2, o);
        float inv2 = rsqrtf(s2 + 1e-6f);
        #pragma unroll
        for (int x = lane; x < 256; x += 32) ks[r*260+x] *= inv2;
    }
    __syncthreads();

    const long cb = ((long)bh*NCH + ch)*CHELEM;
    {
        float* knp = g_kn + cb;
        #pragma unroll 8
        for (int i = 0; i < 32; i++) knp[i*DK+tid] = ks[i*260+tid];
    }

    // ---- Gram (f32x2): acc = (A_ij, attn_ij); warp = 4 i-rows, lane = j ----
    {
        float* atp = g_attn + ((long)bh*NCH + ch)*CC*CC;
        const int i0 = wid*4;
        ull acc[4] = {0,0,0,0};
        #pragma unroll 4
        for (int k4 = 0; k4 < 64; k4++) {
            float4 kj = *(float4*)&ks[lane*260 + k4*4];   // scattered (4 wf)
            ull kj0 = pk2(kj.x, kj.x);
            ull kj1 = pk2(kj.y, kj.y);
            ull kj2 = pk2(kj.z, kj.z);
            ull kj3 = pk2(kj.w, kj.w);
            #pragma unroll
            for (int r = 0; r < 4; r++) {
                float4 ki = *(float4*)&ks[(i0+r)*260 + k4*4];   // broadcast
                float4 qi = *(float4*)&qs[(i0+r)*260 + k4*4];   // broadcast
                ffma2(acc[r], pk2(ki.x,qi.x), kj0);
                ffma2(acc[r], pk2(ki.y,qi.y), kj1);
                ffma2(acc[r], pk2(ki.z,qi.z), kj2);
                ffma2(acc[r], pk2(ki.w,qi.w), kj3);
            }
        }
        #pragma unroll
        for (int r = 0; r < 4; r++) {
            float2 aq = up2(acc[r]);
            if (lane < i0+r) As[(i0+r)*33 + lane] = -bs[i0+r]*aq.x;
            atp[(i0+r)*32 + lane] = (lane <= i0+r) ? aq.y : 0.0f;
        }
    }
    __syncthreads();

    // forward substitution (warp 0): strict-lower T in As
    if (wid == 0) {
        int col = lane;
        for (int i = 1; i < 32; i++) {
            float inc = 0.f;
            if (col < i) for (int j = col+1; j < i; j++) inc += As[i*33+j]*As[j*33+col];
            __syncwarp();
            if (col < i) As[i*33+col] += inc;
            __syncwarp();
        }
    }
    if (wid == 1) {
        float g2 = gs[lane];
        for (int o = 16; o; o >>= 1) g2 += __shfl_xor_sync(~0u, g2, o);
        if (lane == 0) g_gm[bh*NCH + ch] = g2 * (1.0f/32.0f);
    }
    __syncthreads();

    // beta-scale ks in place (per-column)
    #pragma unroll
    for (int j = 0; j < 32; j++) ks[j*260 + tid] *= bs[j];

    // ---- T-apply PASS 1: u_raw = T(beta*v). Only colv[32] live (32 regs). ----
    {
        float colv[32];
        const float* vg = v + tok0*DV;
        #pragma unroll
        for (int j = 0; j < 32; j++) colv[j] = vg[j*DV+tid]*bs[j];
        float* up = g_u + (((long)(bh*8 + (tid>>5))*NCH + ch))*CC*32 + (tid & 31);
        #pragma unroll
        for (int i = 0; i < 32; i++) {
            float accV = colv[i];
            #pragma unroll
            for (int j = 0; j < i; j++) accV += As[i*33+j]*colv[j];
            up[i*32] = accV;
        }
    }

    // ---- T-apply PASS 2: w = T(beta*kn) from smem, write wq incrementally ----
    {
        float* wqp = g_wq + ((long)bh*NCH + ch)*(2*CHELEM) + (long)tid*64;
        #pragma unroll
        for (int i = 0; i < 32; i += 2) {
            float w0 = ks[i*260 + tid];
            #pragma unroll
            for (int j = 0; j < i; j++) w0 += As[i*33+j]*ks[j*260+tid];
            float w1 = ks[(i+1)*260 + tid];
            #pragma unroll
            for (int j = 0; j < i+1; j++) w1 += As[(i+1)*33+j]*ks[j*260+tid];
            *(float4*)&wqp[(i>>1)*4] =
                make_float4(w0, w1, qs[i*260+tid], qs[(i+1)*260+tid]);
        }
    }
}

// ================= persistent scan (round-6 version, unchanged) =================
#define OFF_S   0        // [256][36]      9216
#define OFF_WQ  9216     // [256][64]      16384
#define OFF_K   25600    // [2][32][256]   16384
#define OFF_U   41984    // [2][32][32]    2048
#define OFF_A   44032    // [2][32][32]    2048
#define OFF_RED 46080    // [2][2048]      4096
#define OFF_US  50176    // [32][36]       1152
#define OFF_PO  51328    // [32][36]       1152
#define OFF_MB  52480
#define SCAN_SMEM_FLOATS 52496

#define CHUNK_BYTES (65536u + 32768u + 4096u + 4096u)

__global__ __launch_bounds__(512, 1)
void scan_kernel(float* __restrict__ outp, float* __restrict__ sFinal) {
    extern __shared__ float sm[];
    const uint32_t smb = smem_u32(sm);
    const uint32_t mbar = smb + OFF_MB*4;

    const int tid = threadIdx.x;
    const int bh = blockIdx.y;
    const int v0 = blockIdx.x * 32;

    float* Ss = sm + OFF_S;
    float* us = sm + OFF_US;
    float* po = sm + OFF_PO;

    const long bhoff  = (long)bh*NCH*CHELEM;
    const long bhoff2 = (long)bh*NCH*(2*CHELEM);
    const long ubase  = ((long)(bh*8 + blockIdx.x))*NCH*CC*32;

    const int slice = tid >> 7;
    const int t128  = tid & 127;
    const int cp2   = t128 >> 3;
    const int vp    = t128 & 7;
    const int c0    = cp2*2;
    const int vv    = vp*4;
    const int c_p2 = tid >> 4;
    const int v_p2 = (tid & 15)*2;
    const int kx3 = (tid >> 3)*4;
    const int vv3 = (tid & 7)*4;

    #pragma unroll
    for (int i = 0; i < 18; i++) Ss[tid + i*512] = 0.0f;

    if (tid == 0) mbar_init(mbar, 1);
    asm volatile("fence.proxy.async.shared::cta;" ::: "memory");
    __syncthreads();
    if (tid == 0) {
        mbar_expect(mbar, CHUNK_BYTES);
        bulkcp(smb + OFF_WQ*4, g_wq + bhoff2, 65536u, mbar);
        bulkcp(smb + OFF_K*4,  g_kn + bhoff,  32768u, mbar);
        bulkcp(smb + OFF_U*4,  g_u + ubase,   4096u,  mbar);
        bulkcp(smb + OFF_A*4,  g_attn + (long)bh*NCH*CC*CC, 4096u, mbar);
    }

    for (int t = 0; t < NCH; t++) {
        mbar_wait(mbar, t & 1);
        __syncthreads();

        const int bsel = t & 1;

        if (tid == 0 && t + 1 < NCH) {
            const int tn = t + 1, nb = tn & 1;
            mbar_expect(mbar, CHUNK_BYTES);
            bulkcp(smb + (OFF_K + nb*8192)*4, g_kn + bhoff + (long)tn*CHELEM, 32768u, mbar);
            bulkcp(smb + (OFF_U + nb*1024)*4, g_u + ubase + (long)tn*CC*32,   4096u,  mbar);
            bulkcp(smb + (OFF_A + nb*1024)*4, g_attn + ((long)bh*NCH + tn)*CC*CC, 4096u, mbar);
        }

        const float* wqb = sm + OFF_WQ;

        // ==== phase 1: u = W.S, o = Q.S ====
        ull ua0=0,ua1=0,ua2=0,ua3=0, oa0=0,oa1=0,oa2=0,oa3=0;
        {
            const int kbase = slice*64;
            #pragma unroll 8
            for (int kk = 0; kk < 64; kk++) {
                const int k = kbase + kk;
                float4 s4 = *(const float4*)&Ss[k*36 + vv];
                ull s01 = pk2(s4.x, s4.y), s23 = pk2(s4.z, s4.w);
                float4 wq = *(const float4*)&wqb[k*64 + cp2*4];
                ull wx = pk2(wq.x, wq.x);
                ffma2(ua0, wx, s01); ffma2(ua1, wx, s23);
                ull wy = pk2(wq.y, wq.y);
                ffma2(ua2, wy, s01); ffma2(ua3, wy, s23);
                ull qx = pk2(wq.z, wq.z);
                ffma2(oa0, qx, s01); ffma2(oa1, qx, s23);
                ull qy = pk2(wq.w, wq.w);
                ffma2(oa2, qy, s01); ffma2(oa3, qy, s23);
            }
        }
        if (slice >= 2) {
            float* red = sm + OFF_RED + (slice-2)*2048;
            float2 a0 = up2(ua0), a1 = up2(ua1), a2 = up2(ua2), a3 = up2(ua3);
            float2 b0 = up2(oa0), b1 = up2(oa1), b2 = up2(oa2), b3 = up2(oa3);
            *(float4*)&red[c0*32 + vv]           = make_float4(a0.x,a0.y,a1.x,a1.y);
            *(float4*)&red[(c0+1)*32 + vv]       = make_float4(a2.x,a2.y,a3.x,a3.y);
            *(float4*)&red[1024 + c0*32 + vv]    = make_float4(b0.x,b0.y,b1.x,b1.y);
            *(float4*)&red[1024 + (c0+1)*32 + vv]= make_float4(b2.x,b2.y,b3.x,b3.y);
        }
        __syncthreads();

        if (tid == 0 && t + 1 < NCH) {
            bulkcp(smb + OFF_WQ*4, g_wq + bhoff2 + (long)(t+1)*(2*CHELEM), 65536u, mbar);
        }

        if (slice < 2) {
            const float* red = sm + OFF_RED + slice*2048;
            float4 ru0 = *(const float4*)&red[c0*32 + vv];
            float4 ru1 = *(const float4*)&red[(c0+1)*32 + vv];
            float4 ro0 = *(const float4*)&red[1024 + c0*32 + vv];
            float4 ro1 = *(const float4*)&red[1024 + (c0+1)*32 + vv];
            fadd2(ua0, pk2(ru0.x,ru0.y)); fadd2(ua1, pk2(ru0.z,ru0.w));
            fadd2(ua2, pk2(ru1.x,ru1.y)); fadd2(ua3, pk2(ru1.z,ru1.w));
            fadd2(oa0, pk2(ro0.x,ro0.y)); fadd2(oa1, pk2(ro0.z,ro0.w));
            fadd2(oa2, pk2(ro1.x,ro1.y)); fadd2(oa3, pk2(ro1.z,ro1.w));
        }
        if (slice == 1) {
            float* red = sm + OFF_RED + 2048;
            float2 a0 = up2(ua0), a1 = up2(ua1), a2 = up2(ua2), a3 = up2(ua3);
            float2 b0 = up2(oa0), b1 = up2(oa1), b2 = up2(oa2), b3 = up2(oa3);
            *(float4*)&red[c0*32 + vv]           = make_float4(a0.x,a0.y,a1.x,a1.y);
            *(float4*)&red[(c0+1)*32 + vv]       = make_float4(a2.x,a2.y,a3.x,a3.y);
            *(float4*)&red[1024 + c0*32 + vv]    = make_float4(b0.x,b0.y,b1.x,b1.y);
            *(float4*)&red[1024 + (c0+1)*32 + vv]= make_float4(b2.x,b2.y,b3.x,b3.y);
        }
        __syncthreads();

        if (slice == 0) {
            const float* red = sm + OFF_RED + 2048;
            float4 ru0 = *(const float4*)&red[c0*32 + vv];
            float4 ru1 = *(const float4*)&red[(c0+1)*32 + vv];
            float4 ro0 = *(const float4*)&red[1024 + c0*32 + vv];
            float4 ro1 = *(const float4*)&red[1024 + (c0+1)*32 + vv];
            fadd2(ua0, pk2(ru0.x,ru0.y)); fadd2(ua1, pk2(ru0.z,ru0.w));
            fadd2(ua2, pk2(ru1.x,ru1.y)); fadd2(ua3, pk2(ru1.z,ru1.w));
            fadd2(oa0, pk2(ro0.x,ro0.y)); fadd2(oa1, pk2(ro0.z,ro0.w));
            fadd2(oa2, pk2(ro1.x,ro1.y)); fadd2(oa3, pk2(ro1.z,ro1.w));

            const float* ub = sm + OFF_U + bsel*1024;
            float4 ur0 = *(const float4*)&ub[c0*32 + vv];
            float4 ur1 = *(const float4*)&ub[(c0+1)*32 + vv];
            float2 u0 = up2(ua0), u1 = up2(ua1), u2 = up2(ua2), u3 = up2(ua3);
            *(float4*)&us[c0*36 + vv] =
                make_float4(ur0.x-u0.x, ur0.y-u0.y, ur0.z-u1.x, ur0.w-u1.y);
            *(float4*)&us[(c0+1)*36 + vv] =
                make_float4(ur1.x-u2.x, ur1.y-u2.y, ur1.z-u3.x, ur1.w-u3.y);
            float2 o0 = up2(oa0), o1 = up2(oa1), o2 = up2(oa2), o3 = up2(oa3);
            *(float4*)&po[c0*36 + vv]     = make_float4(o0.x,o0.y,o1.x,o1.y);
            *(float4*)&po[(c0+1)*36 + vv] = make_float4(o2.x,o2.y,o3.x,o3.y);
        }
        __syncthreads();

        // ==== phase 2: o = po + attn.u (triangular) ====
        {
            const float* ab = sm + OFF_A + bsel*1024;
            float2 pv = *(const float2*)&po[c_p2*36 + v_p2];
            ull oacc = pk2(pv.x, pv.y);
            #pragma unroll 4
            for (int d = 0; d <= c_p2; d++) {
                float2 u2 = *(const float2*)&us[d*36 + v_p2];
                float av = ab[c_p2*32 + d];
                ffma2(oacc, pk2(av, av), pk2(u2.x, u2.y));
            }
            float2 r = up2(oacc);
            *(float2*)(outp + ((long)bh*LSEQ + (long)t*CC + c_p2)*DV + v0 + v_p2) = r;
        }

        // ==== phase 3: S = gm*S + kn^T.u ====
        {
            const float* kb = sm + OFF_K + bsel*8192;
            ull acc0=0,acc1=0,acc2=0,acc3=0,acc4=0,acc5=0,acc6=0,acc7=0;
            #pragma unroll 4
            for (int c = 0; c < 32; c++) {
                float4 kv4 = *(const float4*)&kb[c*256 + kx3];
                float4 u4  = *(const float4*)&us[c*36 + vv3];
                ull u01 = pk2(u4.x, u4.y), u23 = pk2(u4.z, u4.w);
                ull p0 = pk2(kv4.x, kv4.x); ffma2(acc0, p0, u01); ffma2(acc1, p0, u23);
                ull p1 = pk2(kv4.y, kv4.y); ffma2(acc2, p1, u01); ffma2(acc3, p1, u23);
                ull p2 = pk2(kv4.z, kv4.z); ffma2(acc4, p2, u01); ffma2(acc5, p2, u23);
                ull p3 = pk2(kv4.w, kv4.w); ffma2(acc6, p3, u01); ffma2(acc7, p3, u23);
            }
            const float gm = g_gm[bh*NCH + t];
            const ull gmp = pk2(gm, gm);
            const bool last = (t == NCH-1);
            float* sfp = sFinal + (long)bh*DK*DV;
            #pragma unroll
            for (int r = 0; r < 4; r++) {
                const int row = kx3 + r;
                ulonglong2 so = *(const ulonglong2*)&Ss[row*36 + vv3];
                ull n0, n1;
                switch (r) {
                    case 0: n0 = acc0; n1 = acc1; break;
                    case 1: n0 = acc2; n1 = acc3; break;
                    case 2: n0 = acc4; n1 = acc5; break;
                    default: n0 = acc6; n1 = acc7; break;
                }
                ffma2(n0, so.x, gmp);
                ffma2(n1, so.y, gmp);
                ulonglong2 sn; sn.x = n0; sn.y = n1;
                *(ulonglong2*)&Ss[row*36 + vv3] = sn;
                if (last) *(ulonglong2*)&sfp[(long)row*DV + v0 + vv3] = sn;
            }
        }
    }
}

// ================= launch =================
extern "C" void kernel_launch(void* const* d_in, const int* in_sizes, int n_in,
                              void* d_out, int out_size) {
    const float* q     = (const float*)d_in[0];
    const float* k     = (const float*)d_in[1];
    const float* v     = (const float*)d_in[2];
    const float* beta  = (const float*)d_in[3];
    const float* gamma = (const float*)d_in[4];
    float* outp = (float*)d_out;
    float* sfin = outp + (long)BHn*LSEQ*DV;
    cudaFuncSetAttribute(pre_kernel,  cudaFuncAttributeMaxDynamicSharedMemorySize, PRE_SMEM_FLOATS*4);
    cudaFuncSetAttribute(scan_kernel, cudaFuncAttributeMaxDynamicSharedMemorySize, SCAN_SMEM_FLOATS*4);
    (void)in_sizes; (void)n_in; (void)out_size;
    pre_kernel<<<BHn*NCH, 256, PRE_SMEM_FLOATS*4>>>(q, k, v, beta, gamma);
    scan_kernel<<<dim3(8, BHn), 512, SCAN_SMEM_FLOATS*4>>>(outp, sfin);
}

// round 14
// speedup vs baseline: 1.0516x; 1.0516x over previous
#include <cuda_runtime.h>
#include <cuda_bf16.h>
#include <cstdint>

// DeltaNet chunkwise delta-rule linear attention with decay.
// Round 14: scan = round-6 exactly (785-789us x5). Pre = round-6 body with
// vectorized float4 global loads and v staged into smem up-front (latency
// hidden behind norm/Gram/forward-substitution).

#define BHn 16
#define LSEQ 4096
#define DK 256
#define DV 256
#define CC 32
#define NCH 128
#define CHELEM (CC*DK)

__device__ float g_wq[BHn*NCH*2*CHELEM];   // [bh][ch][k][64] {w2c,w2c+1,q2c,q2c+1}
__device__ float g_kn[BHn*NCH*CHELEM];     // [bh][ch][c][k]
__device__ float g_u [BHn*8*NCH*CC*32];    // [bh][vblk][ch][c][32]
__device__ float g_attn[BHn*NCH*CC*CC];    // [bh][ch][c][d], zero d>c
__device__ float g_gm[BHn*NCH];

typedef unsigned long long ull;
__device__ __forceinline__ void ffma2(ull &d, ull a, ull b) {
    asm("fma.rn.f32x2 %0, %1, %2, %0;" : "+l"(d) : "l"(a), "l"(b));
}
__device__ __forceinline__ void fadd2(ull &d, ull a) {
    asm("add.rn.f32x2 %0, %0, %1;" : "+l"(d) : "l"(a));
}
__device__ __forceinline__ ull pk2(float a, float b) {
    ull r; asm("mov.b64 %0, {%1, %2};" : "=l"(r) : "f"(a), "f"(b)); return r;
}
__device__ __forceinline__ float2 up2(ull p) {
    float2 r; asm("mov.b64 {%0, %1}, %2;" : "=f"(r.x), "=f"(r.y) : "l"(p)); return r;
}
__device__ __forceinline__ uint32_t smem_u32(const void* p) {
    uint32_t a;
    asm("{ .reg .u64 t; cvta.to.shared.u64 t, %1; cvt.u32.u64 %0, t; }" : "=r"(a) : "l"(p));
    return a;
}
__device__ __forceinline__ void bulkcp(uint32_t dst, const void* src, uint32_t bytes, uint32_t mbar) {
    asm volatile("cp.async.bulk.shared::cluster.global.mbarrier::complete_tx::bytes [%0], [%1], %2, [%3];"
                 :: "r"(dst), "l"(src), "r"(bytes), "r"(mbar) : "memory");
}
__device__ __forceinline__ void mbar_init(uint32_t mbar, uint32_t cnt) {
    asm volatile("mbarrier.init.shared.b64 [%0], %1;" :: "r"(mbar), "r"(cnt) : "memory");
}
__device__ __forceinline__ void mbar_expect(uint32_t mbar, uint32_t bytes) {
    asm volatile("mbarrier.arrive.expect_tx.shared.b64 _, [%0], %1;" :: "r"(mbar), "r"(bytes) : "memory");
}
__device__ __forceinline__ void mbar_wait(uint32_t mbar, uint32_t parity) {
    uint32_t done;
    asm volatile("{\n\t.reg .pred p;\n\t"
        "mbarrier.try_wait.parity.acquire.cta.shared::cta.b64 p, [%1], %2;\n\t"
        "selp.b32 %0, 1, 0, p;\n\t}" : "=r"(done) : "r"(mbar), "r"(parity) : "memory");
    if (!done) {
        asm volatile("{\n\t.reg .pred P1;\n\t"
            "WL_%=:\n\t"
            "mbarrier.try_wait.parity.acquire.cta.shared::cta.b64 P1, [%0], %1, 0x989680;\n\t"
            "@P1 bra.uni WD_%=;\n\t"
            "bra.uni WL_%=;\n\t"
            "WD_%=:\n\t}" :: "r"(mbar), "r"(parity) : "memory");
    }
}

// ================= pre (round-6 body + vectorized/staged loads) =================
// smem: qs[32*260] | ks[32*260] | vs[32*260] | As[32*33] | bs[32] | gs[32]
#define PRE_SMEM_FLOATS (8320+8320+8320+1056+32+32)

__global__ __launch_bounds__(256, 2)
void pre_kernel(const float* __restrict__ q, const float* __restrict__ k,
                const float* __restrict__ v, const float* __restrict__ beta,
                const float* __restrict__ gamma) {
    extern __shared__ float sm[];
    float* qs = sm;
    float* ks = sm + 8320;
    float* vs = sm + 16640;
    float* As = sm + 24960;
    float* bs = sm + 26016;
    float* gs = sm + 26048;

    const int tid = threadIdx.x, lane = tid & 31, wid = tid >> 5;
    const int bh = blockIdx.x >> 7, ch = blockIdx.x & 127;
    const long tok0 = (long)bh*LSEQ + (long)ch*CC;
    const float* qg = q + tok0*DK;
    const float* kg = k + tok0*DK;
    const float* vg = v + tok0*DV;

    // ---- vectorized staging: q, k, v via float4 (issued up-front, deep MLP) ----
    #pragma unroll
    for (int it = 0; it < 8; it++) {
        int idx = tid + it*256;            // 0..2047 float4s
        int row = idx >> 6, col = (idx & 63)*4;
        float4 qv4 = *(const float4*)&qg[row*DK + col];
        float4 kv4 = *(const float4*)&kg[row*DK + col];
        float4 vv4 = *(const float4*)&vg[row*DV + col];
        *(float4*)&qs[row*260 + col] = qv4;
        *(float4*)&ks[row*260 + col] = kv4;
        *(float4*)&vs[row*260 + col] = vv4;
    }
    if (tid < 32) { bs[tid] = beta[tok0+tid]; gs[tid] = gamma[tok0+tid]; }
    __syncthreads();

    // l2 normalize rows (warp per row)
    for (int r = wid; r < 32; r += 8) {
        float s = 0.f;
        #pragma unroll
        for (int x = lane; x < 256; x += 32) { float t = qs[r*260+x]; s += t*t; }
        for (int o = 16; o; o >>= 1) s += __shfl_xor_sync(~0u, s, o);
        float inv = rsqrtf(s + 1e-6f);
        #pragma unroll
        for (int x = lane; x < 256; x += 32) qs[r*260+x] *= inv;
        float s2 = 0.f;
        #pragma unroll
        for (int x = lane; x < 256; x += 32) { float t = ks[r*260+x]; s2 += t*t; }
        for (int o = 16; o; o >>= 1) s2 += __shfl_xor_sync(~0u, s2, o);
        float inv2 = rsqrtf(s2 + 1e-6f);
        #pragma unroll
        for (int x = lane; x < 256; x += 32) ks[r*260+x] *= inv2;
    }
    __syncthreads();

    const long cb = ((long)bh*NCH + ch)*CHELEM;
    {
        float* knp = g_kn + cb;
        #pragma unroll 8
        for (int i = 0; i < 32; i++) knp[i*DK+tid] = ks[i*260+tid];
    }

    // ---- Gram: warp = rows i0..i0+3, lane = j ----
    {
        float* atp = g_attn + ((long)bh*NCH + ch)*CC*CC;
        const int i0 = wid*4;
        float aA[4] = {0,0,0,0}, aQ[4] = {0,0,0,0};
        #pragma unroll 4
        for (int k4 = 0; k4 < 64; k4++) {
            float4 kj = *(float4*)&ks[lane*260 + k4*4];
            #pragma unroll
            for (int r = 0; r < 4; r++) {
                float4 ki = *(float4*)&ks[(i0+r)*260 + k4*4];
                float4 qi = *(float4*)&qs[(i0+r)*260 + k4*4];
                aA[r] += ki.x*kj.x + ki.y*kj.y + ki.z*kj.z + ki.w*kj.w;
                aQ[r] += qi.x*kj.x + qi.y*kj.y + qi.z*kj.z + qi.w*kj.w;
            }
        }
        #pragma unroll
        for (int r = 0; r < 4; r++) {
            if (lane < i0+r) As[(i0+r)*33 + lane] = -bs[i0+r]*aA[r];
            atp[(i0+r)*32 + lane] = (lane <= i0+r) ? aQ[r] : 0.0f;
        }
    }
    __syncthreads();

    // forward substitution (warp 0): strict-lower T in As
    if (wid == 0) {
        int col = lane;
        for (int i = 1; i < 32; i++) {
            float inc = 0.f;
            if (col < i) for (int j = col+1; j < i; j++) inc += As[i*33+j]*As[j*33+col];
            __syncwarp();
            if (col < i) As[i*33+col] += inc;
            __syncwarp();
        }
    }
    if (wid == 1) {
        float g2 = gs[lane];
        for (int o = 16; o; o >>= 1) g2 += __shfl_xor_sync(~0u, g2, o);
        if (lane == 0) g_gm[bh*NCH + ch] = g2 * (1.0f/32.0f);
    }
    __syncthreads();

    // beta-scale ks in place (per-column)
    #pragma unroll
    for (int j = 0; j < 32; j++) ks[j*260 + tid] *= bs[j];

    // ---- fused T-apply: u_raw = T(beta*v), w = T(beta*kn) ----
    {
        float colv[32];
        #pragma unroll
        for (int j = 0; j < 32; j++) colv[j] = vs[j*260+tid]*bs[j];   // LDS, staged early
        float* up = g_u + (((long)(bh*8 + (tid>>5))*NCH + ch))*CC*32 + (tid & 31);
        float wout[32];
        #pragma unroll
        for (int i = 0; i < 32; i++) {
            float accV = colv[i], accK = ks[i*260+tid];
            #pragma unroll
            for (int j = 0; j < i; j++) {
                float a = As[i*33+j];
                accV += a*colv[j]; accK += a*ks[j*260+tid];
            }
            up[i*32] = accV; wout[i] = accK;
        }
        float* wqp = g_wq + ((long)bh*NCH + ch)*(2*CHELEM) + (long)tid*64;
        #pragma unroll
        for (int cp = 0; cp < 16; cp++)
            *(float4*)&wqp[cp*4] = make_float4(wout[2*cp], wout[2*cp+1],
                                               qs[(2*cp)*260+tid], qs[(2*cp+1)*260+tid]);
    }
}

// ================= persistent scan (round-6 version, unchanged) =================
#define OFF_S   0        // [256][36]      9216
#define OFF_WQ  9216     // [256][64]      16384
#define OFF_K   25600    // [2][32][256]   16384
#define OFF_U   41984    // [2][32][32]    2048
#define OFF_A   44032    // [2][32][32]    2048
#define OFF_RED 46080    // [2][2048]      4096
#define OFF_US  50176    // [32][36]       1152
#define OFF_PO  51328    // [32][36]       1152
#define OFF_MB  52480
#define SCAN_SMEM_FLOATS 52496

#define CHUNK_BYTES (65536u + 32768u + 4096u + 4096u)

__global__ __launch_bounds__(512, 1)
void scan_kernel(float* __restrict__ outp, float* __restrict__ sFinal) {
    extern __shared__ float sm[];
    const uint32_t smb = smem_u32(sm);
    const uint32_t mbar = smb + OFF_MB*4;

    const int tid = threadIdx.x;
    const int bh = blockIdx.y;
    const int v0 = blockIdx.x * 32;

    float* Ss = sm + OFF_S;
    float* us = sm + OFF_US;
    float* po = sm + OFF_PO;

    const long bhoff  = (long)bh*NCH*CHELEM;
    const long bhoff2 = (long)bh*NCH*(2*CHELEM);
    const long ubase  = ((long)(bh*8 + blockIdx.x))*NCH*CC*32;

    const int slice = tid >> 7;
    const int t128  = tid & 127;
    const int cp2   = t128 >> 3;
    const int vp    = t128 & 7;
    const int c0    = cp2*2;
    const int vv    = vp*4;
    const int c_p2 = tid >> 4;
    const int v_p2 = (tid & 15)*2;
    const int kx3 = (tid >> 3)*4;
    const int vv3 = (tid & 7)*4;

    #pragma unroll
    for (int i = 0; i < 18; i++) Ss[tid + i*512] = 0.0f;

    if (tid == 0) mbar_init(mbar, 1);
    asm volatile("fence.proxy.async.shared::cta;" ::: "memory");
    __syncthreads();
    if (tid == 0) {
        mbar_expect(mbar, CHUNK_BYTES);
        bulkcp(smb + OFF_WQ*4, g_wq + bhoff2, 65536u, mbar);
        bulkcp(smb + OFF_K*4,  g_kn + bhoff,  32768u, mbar);
        bulkcp(smb + OFF_U*4,  g_u + ubase,   4096u,  mbar);
        bulkcp(smb + OFF_A*4,  g_attn + (long)bh*NCH*CC*CC, 4096u, mbar);
    }

    for (int t = 0; t < NCH; t++) {
        mbar_wait(mbar, t & 1);
        __syncthreads();

        const int bsel = t & 1;

        if (tid == 0 && t + 1 < NCH) {
            const int tn = t + 1, nb = tn & 1;
            mbar_expect(mbar, CHUNK_BYTES);
            bulkcp(smb + (OFF_K + nb*8192)*4, g_kn + bhoff + (long)tn*CHELEM, 32768u, mbar);
            bulkcp(smb + (OFF_U + nb*1024)*4, g_u + ubase + (long)tn*CC*32,   4096u,  mbar);
            bulkcp(smb + (OFF_A + nb*1024)*4, g_attn + ((long)bh*NCH + tn)*CC*CC, 4096u, mbar);
        }

        const float* wqb = sm + OFF_WQ;

        // ==== phase 1: u = W.S, o = Q.S ====
        ull ua0=0,ua1=0,ua2=0,ua3=0, oa0=0,oa1=0,oa2=0,oa3=0;
        {
            const int kbase = slice*64;
            #pragma unroll 8
            for (int kk = 0; kk < 64; kk++) {
                const int k = kbase + kk;
                float4 s4 = *(const float4*)&Ss[k*36 + vv];
                ull s01 = pk2(s4.x, s4.y), s23 = pk2(s4.z, s4.w);
                float4 wq = *(const float4*)&wqb[k*64 + cp2*4];
                ull wx = pk2(wq.x, wq.x);
                ffma2(ua0, wx, s01); ffma2(ua1, wx, s23);
                ull wy = pk2(wq.y, wq.y);
                ffma2(ua2, wy, s01); ffma2(ua3, wy, s23);
                ull qx = pk2(wq.z, wq.z);
                ffma2(oa0, qx, s01); ffma2(oa1, qx, s23);
                ull qy = pk2(wq.w, wq.w);
                ffma2(oa2, qy, s01); ffma2(oa3, qy, s23);
            }
        }
        if (slice >= 2) {
            float* red = sm + OFF_RED + (slice-2)*2048;
            float2 a0 = up2(ua0), a1 = up2(ua1), a2 = up2(ua2), a3 = up2(ua3);
            float2 b0 = up2(oa0), b1 = up2(oa1), b2 = up2(oa2), b3 = up2(oa3);
            *(float4*)&red[c0*32 + vv]           = make_float4(a0.x,a0.y,a1.x,a1.y);
            *(float4*)&red[(c0+1)*32 + vv]       = make_float4(a2.x,a2.y,a3.x,a3.y);
            *(float4*)&red[1024 + c0*32 + vv]    = make_float4(b0.x,b0.y,b1.x,b1.y);
            *(float4*)&red[1024 + (c0+1)*32 + vv]= make_float4(b2.x,b2.y,b3.x,b3.y);
        }
        __syncthreads();

        if (tid == 0 && t + 1 < NCH) {
            bulkcp(smb + OFF_WQ*4, g_wq + bhoff2 + (long)(t+1)*(2*CHELEM), 65536u, mbar);
        }

        if (slice < 2) {
            const float* red = sm + OFF_RED + slice*2048;
            float4 ru0 = *(const float4*)&red[c0*32 + vv];
            float4 ru1 = *(const float4*)&red[(c0+1)*32 + vv];
            float4 ro0 = *(const float4*)&red[1024 + c0*32 + vv];
            float4 ro1 = *(const float4*)&red[1024 + (c0+1)*32 + vv];
            fadd2(ua0, pk2(ru0.x,ru0.y)); fadd2(ua1, pk2(ru0.z,ru0.w));
            fadd2(ua2, pk2(ru1.x,ru1.y)); fadd2(ua3, pk2(ru1.z,ru1.w));
            fadd2(oa0, pk2(ro0.x,ro0.y)); fadd2(oa1, pk2(ro0.z,ro0.w));
            fadd2(oa2, pk2(ro1.x,ro1.y)); fadd2(oa3, pk2(ro1.z,ro1.w));
        }
        if (slice == 1) {
            float* red = sm + OFF_RED + 2048;
            float2 a0 = up2(ua0), a1 = up2(ua1), a2 = up2(ua2), a3 = up2(ua3);
            float2 b0 = up2(oa0), b1 = up2(oa1), b2 = up2(oa2), b3 = up2(oa3);
            *(float4*)&red[c0*32 + vv]           = make_float4(a0.x,a0.y,a1.x,a1.y);
            *(float4*)&red[(c0+1)*32 + vv]       = make_float4(a2.x,a2.y,a3.x,a3.y);
            *(float4*)&red[1024 + c0*32 + vv]    = make_float4(b0.x,b0.y,b1.x,b1.y);
            *(float4*)&red[1024 + (c0+1)*32 + vv]= make_float4(b2.x,b2.y,b3.x,b3.y);
        }
        __syncthreads();

        if (slice == 0) {
            const float* red = sm + OFF_RED + 2048;
            float4 ru0 = *(const float4*)&red[c0*32 + vv];
            float4 ru1 = *(const float4*)&red[(c0+1)*32 + vv];
            float4 ro0 = *(const float4*)&red[1024 + c0*32 + vv];
            float4 ro1 = *(const float4*)&red[1024 + (c0+1)*32 + vv];
            fadd2(ua0, pk2(ru0.x,ru0.y)); fadd2(ua1, pk2(ru0.z,ru0.w));
            fadd2(ua2, pk2(ru1.x,ru1.y)); fadd2(ua3, pk2(ru1.z,ru1.w));
            fadd2(oa0, pk2(ro0.x,ro0.y)); fadd2(oa1, pk2(ro0.z,ro0.w));
            fadd2(oa2, pk2(ro1.x,ro1.y)); fadd2(oa3, pk2(ro1.z,ro1.w));

            const float* ub = sm + OFF_U + bsel*1024;
            float4 ur0 = *(const float4*)&ub[c0*32 + vv];
            float4 ur1 = *(const float4*)&ub[(c0+1)*32 + vv];
            float2 u0 = up2(ua0), u1 = up2(ua1), u2 = up2(ua2), u3 = up2(ua3);
            *(float4*)&us[c0*36 + vv] =
                make_float4(ur0.x-u0.x, ur0.y-u0.y, ur0.z-u1.x, ur0.w-u1.y);
            *(float4*)&us[(c0+1)*36 + vv] =
                make_float4(ur1.x-u2.x, ur1.y-u2.y, ur1.z-u3.x, ur1.w-u3.y);
            float2 o0 = up2(oa0), o1 = up2(oa1), o2 = up2(oa2), o3 = up2(oa3);
            *(float4*)&po[c0*36 + vv]     = make_float4(o0.x,o0.y,o1.x,o1.y);
            *(float4*)&po[(c0+1)*36 + vv] = make_float4(o2.x,o2.y,o3.x,o3.y);
        }
        __syncthreads();

        // ==== phase 2: o = po + attn.u (triangular) ====
        {
            const float* ab = sm + OFF_A + bsel*1024;
            float2 pv = *(const float2*)&po[c_p2*36 + v_p2];
            ull oacc = pk2(pv.x, pv.y);
            #pragma unroll 4
            for (int d = 0; d <= c_p2; d++) {
                float2 u2 = *(const float2*)&us[d*36 + v_p2];
                float av = ab[c_p2*32 + d];
                ffma2(oacc, pk2(av, av), pk2(u2.x, u2.y));
            }
            float2 r = up2(oacc);
            *(float2*)(outp + ((long)bh*LSEQ + (long)t*CC + c_p2)*DV + v0 + v_p2) = r;
        }

        // ==== phase 3: S = gm*S + kn^T.u ====
        {
            const float* kb = sm + OFF_K + bsel*8192;
            ull acc0=0,acc1=0,acc2=0,acc3=0,acc4=0,acc5=0,acc6=0,acc7=0;
            #pragma unroll 4
            for (int c = 0; c < 32; c++) {
                float4 kv4 = *(const float4*)&kb[c*256 + kx3];
                float4 u4  = *(const float4*)&us[c*36 + vv3];
                ull u01 = pk2(u4.x, u4.y), u23 = pk2(u4.z, u4.w);
                ull p0 = pk2(kv4.x, kv4.x); ffma2(acc0, p0, u01); ffma2(acc1, p0, u23);
                ull p1 = pk2(kv4.y, kv4.y); ffma2(acc2, p1, u01); ffma2(acc3, p1, u23);
                ull p2 = pk2(kv4.z, kv4.z); ffma2(acc4, p2, u01); ffma2(acc5, p2, u23);
                ull p3 = pk2(kv4.w, kv4.w); ffma2(acc6, p3, u01); ffma2(acc7, p3, u23);
            }
            const float gm = g_gm[bh*NCH + t];
            const ull gmp = pk2(gm, gm);
            const bool last = (t == NCH-1);
            float* sfp = sFinal + (long)bh*DK*DV;
            #pragma unroll
            for (int r = 0; r < 4; r++) {
                const int row = kx3 + r;
                ulonglong2 so = *(const ulonglong2*)&Ss[row*36 + vv3];
                ull n0, n1;
                switch (r) {
                    case 0: n0 = acc0; n1 = acc1; break;
                    case 1: n0 = acc2; n1 = acc3; break;
                    case 2: n0 = acc4; n1 = acc5; break;
                    default: n0 = acc6; n1 = acc7; break;
                }
                ffma2(n0, so.x, gmp);
                ffma2(n1, so.y, gmp);
                ulonglong2 sn; sn.x = n0; sn.y = n1;
                *(ulonglong2*)&Ss[row*36 + vv3] = sn;
                if (last) *(ulonglong2*)&sfp[(long)row*DV + v0 + vv3] = sn;
            }
        }
    }
}

// ================= launch =================
extern "C" void kernel_launch(void* const* d_in, const int* in_sizes, int n_in,
                              void* d_out, int out_size) {
    const float* q     = (const float*)d_in[0];
    const float* k     = (const float*)d_in[1];
    const float* v     = (const float*)d_in[2];
    const float* beta  = (const float*)d_in[3];
    const float* gamma = (const float*)d_in[4];
    float* outp = (float*)d_out;
    float* sfin = outp + (long)BHn*LSEQ*DV;
    cudaFuncSetAttribute(pre_kernel,  cudaFuncAttributeMaxDynamicSharedMemorySize, PRE_SMEM_FLOATS*4);
    cudaFuncSetAttribute(scan_kernel, cudaFuncAttributeMaxDynamicSharedMemorySize, SCAN_SMEM_FLOATS*4);
    (void)in_sizes; (void)n_in; (void)out_size;
    pre_kernel<<<BHn*NCH, 256, PRE_SMEM_FLOATS*4>>>(q, k, v, beta, gamma);
    scan_kernel<<<dim3(8, BHn), 512, SCAN_SMEM_FLOATS*4>>>(outp, sfin);
}

// round 15
// speedup vs baseline: 1.0678x; 1.0154x over previous
#include <cuda_runtime.h>
#include <cuda_bf16.h>
#include <cstdint>

// DeltaNet chunkwise delta-rule linear attention with decay.
// Final: exact round-6 configuration — the measured-best artifact (1038.8us).
//  pre_kernel  : per-chunk precompute (norms, T via forward subst, u_raw, w, attn, gm).
//  scan_kernel : ONE persistent launch, 128 CTAs (16bh x 8 vblk), 512 thr.
//                cp.async.bulk (TMA) + mbarrier operand prefetch; f32x2 GEMM phases.

#define BHn 16
#define LSEQ 4096
#define DK 256
#define DV 256
#define CC 32
#define NCH 128
#define CHELEM (CC*DK)

__device__ float g_wq[BHn*NCH*2*CHELEM];   // [bh][ch][k][64] {w2c,w2c+1,q2c,q2c+1}
__device__ float g_kn[BHn*NCH*CHELEM];     // [bh][ch][c][k]
__device__ float g_u [BHn*8*NCH*CC*32];    // [bh][vblk][ch][c][32]
__device__ float g_attn[BHn*NCH*CC*CC];    // [bh][ch][c][d], zero d>c
__device__ float g_gm[BHn*NCH];

typedef unsigned long long ull;
__device__ __forceinline__ void ffma2(ull &d, ull a, ull b) {
    asm("fma.rn.f32x2 %0, %1, %2, %0;" : "+l"(d) : "l"(a), "l"(b));
}
__device__ __forceinline__ void fadd2(ull &d, ull a) {
    asm("add.rn.f32x2 %0, %0, %1;" : "+l"(d) : "l"(a));
}
__device__ __forceinline__ ull pk2(float a, float b) {
    ull r; asm("mov.b64 %0, {%1, %2};" : "=l"(r) : "f"(a), "f"(b)); return r;
}
__device__ __forceinline__ float2 up2(ull p) {
    float2 r; asm("mov.b64 {%0, %1}, %2;" : "=f"(r.x), "=f"(r.y) : "l"(p)); return r;
}
__device__ __forceinline__ uint32_t smem_u32(const void* p) {
    uint32_t a;
    asm("{ .reg .u64 t; cvta.to.shared.u64 t, %1; cvt.u32.u64 %0, t; }" : "=r"(a) : "l"(p));
    return a;
}
__device__ __forceinline__ void bulkcp(uint32_t dst, const void* src, uint32_t bytes, uint32_t mbar) {
    asm volatile("cp.async.bulk.shared::cluster.global.mbarrier::complete_tx::bytes [%0], [%1], %2, [%3];"
                 :: "r"(dst), "l"(src), "r"(bytes), "r"(mbar) : "memory");
}
__device__ __forceinline__ void mbar_init(uint32_t mbar, uint32_t cnt) {
    asm volatile("mbarrier.init.shared.b64 [%0], %1;" :: "r"(mbar), "r"(cnt) : "memory");
}
__device__ __forceinline__ void mbar_expect(uint32_t mbar, uint32_t bytes) {
    asm volatile("mbarrier.arrive.expect_tx.shared.b64 _, [%0], %1;" :: "r"(mbar), "r"(bytes) : "memory");
}
__device__ __forceinline__ void mbar_wait(uint32_t mbar, uint32_t parity) {
    uint32_t done;
    asm volatile("{\n\t.reg .pred p;\n\t"
        "mbarrier.try_wait.parity.acquire.cta.shared::cta.b64 p, [%1], %2;\n\t"
        "selp.b32 %0, 1, 0, p;\n\t}" : "=r"(done) : "r"(mbar), "r"(parity) : "memory");
    if (!done) {
        asm volatile("{\n\t.reg .pred P1;\n\t"
            "WL_%=:\n\t"
            "mbarrier.try_wait.parity.acquire.cta.shared::cta.b64 P1, [%0], %1, 0x989680;\n\t"
            "@P1 bra.uni WD_%=;\n\t"
            "bra.uni WL_%=;\n\t"
            "WD_%=:\n\t}" :: "r"(mbar), "r"(parity) : "memory");
    }
}

// ================= pre (round-6 version) =================
#define PRE_SMEM_FLOATS (8320+8320+1056+32+32)

__global__ __launch_bounds__(256, 2)
void pre_kernel(const float* __restrict__ q, const float* __restrict__ k,
                const float* __restrict__ v, const float* __restrict__ beta,
                const float* __restrict__ gamma) {
    extern __shared__ float sm[];
    float* qs = sm; float* ks = sm + 8320; float* As = sm + 16640;
    float* bs = sm + 17696; float* gs = sm + 17728;

    const int tid = threadIdx.x, lane = tid & 31, wid = tid >> 5;
    const int bh = blockIdx.x >> 7, ch = blockIdx.x & 127;
    const long tok0 = (long)bh*LSEQ + (long)ch*CC;
    const float* qg = q + tok0*DK;
    const float* kg = k + tok0*DK;

    #pragma unroll 8
    for (int i = 0; i < 32; i++) {
        qs[i*260+tid] = qg[i*DK+tid];
        ks[i*260+tid] = kg[i*DK+tid];
    }
    if (tid < 32) { bs[tid] = beta[tok0+tid]; gs[tid] = gamma[tok0+tid]; }
    __syncthreads();

    for (int r = wid; r < 32; r += 8) {
        float s = 0.f;
        #pragma unroll
        for (int x = lane; x < 256; x += 32) { float t = qs[r*260+x]; s += t*t; }
        for (int o = 16; o; o >>= 1) s += __shfl_xor_sync(~0u, s, o);
        float inv = rsqrtf(s + 1e-6f);
        #pragma unroll
        for (int x = lane; x < 256; x += 32) qs[r*260+x] *= inv;
        float s2 = 0.f;
        #pragma unroll
        for (int x = lane; x < 256; x += 32) { float t = ks[r*260+x]; s2 += t*t; }
        for (int o = 16; o; o >>= 1) s2 += __shfl_xor_sync(~0u, s2, o);
        float inv2 = rsqrtf(s2 + 1e-6f);
        #pragma unroll
        for (int x = lane; x < 256; x += 32) ks[r*260+x] *= inv2;
    }
    __syncthreads();

    const long cb = ((long)bh*NCH + ch)*CHELEM;
    {
        float* knp = g_kn + cb;
        #pragma unroll 8
        for (int i = 0; i < 32; i++) knp[i*DK+tid] = ks[i*260+tid];
    }

    {
        float* atp = g_attn + ((long)bh*NCH + ch)*CC*CC;
        const int i0 = wid*4;
        float aA[4] = {0,0,0,0}, aQ[4] = {0,0,0,0};
        #pragma unroll 4
        for (int k4 = 0; k4 < 64; k4++) {
            float4 kj = *(float4*)&ks[lane*260 + k4*4];
            #pragma unroll
            for (int r = 0; r < 4; r++) {
                float4 ki = *(float4*)&ks[(i0+r)*260 + k4*4];
                float4 qi = *(float4*)&qs[(i0+r)*260 + k4*4];
                aA[r] += ki.x*kj.x + ki.y*kj.y + ki.z*kj.z + ki.w*kj.w;
                aQ[r] += qi.x*kj.x + qi.y*kj.y + qi.z*kj.z + qi.w*kj.w;
            }
        }
        #pragma unroll
        for (int r = 0; r < 4; r++) {
            if (lane < i0+r) As[(i0+r)*33 + lane] = -bs[i0+r]*aA[r];
            atp[(i0+r)*32 + lane] = (lane <= i0+r) ? aQ[r] : 0.0f;
        }
    }
    __syncthreads();

    if (wid == 0) {
        int col = lane;
        for (int i = 1; i < 32; i++) {
            float inc = 0.f;
            if (col < i) for (int j = col+1; j < i; j++) inc += As[i*33+j]*As[j*33+col];
            __syncwarp();
            if (col < i) As[i*33+col] += inc;
            __syncwarp();
        }
    }
    if (wid == 1) {
        float g2 = gs[lane];
        for (int o = 16; o; o >>= 1) g2 += __shfl_xor_sync(~0u, g2, o);
        if (lane == 0) g_gm[bh*NCH + ch] = g2 * (1.0f/32.0f);
    }
    __syncthreads();

    #pragma unroll
    for (int j = 0; j < 32; j++) ks[j*260 + tid] *= bs[j];

    {
        float colv[32];
        const float* vg = v + tok0*DV;
        #pragma unroll
        for (int j = 0; j < 32; j++) colv[j] = vg[j*DV+tid]*bs[j];
        float* up = g_u + (((long)(bh*8 + (tid>>5))*NCH + ch))*CC*32 + (tid & 31);
        float wout[32];
        #pragma unroll
        for (int i = 0; i < 32; i++) {
            float accV = colv[i], accK = ks[i*260+tid];
            #pragma unroll
            for (int j = 0; j < i; j++) {
                float a = As[i*33+j];
                accV += a*colv[j]; accK += a*ks[j*260+tid];
            }
            up[i*32] = accV; wout[i] = accK;
        }
        float* wqp = g_wq + ((long)bh*NCH + ch)*(2*CHELEM) + (long)tid*64;
        #pragma unroll
        for (int cp = 0; cp < 16; cp++)
            *(float4*)&wqp[cp*4] = make_float4(wout[2*cp], wout[2*cp+1],
                                               qs[(2*cp)*260+tid], qs[(2*cp+1)*260+tid]);
    }
}

// ================= persistent scan (round-6 version) =================
#define OFF_S   0        // [256][36]      9216
#define OFF_WQ  9216     // [256][64]      16384
#define OFF_K   25600    // [2][32][256]   16384
#define OFF_U   41984    // [2][32][32]    2048
#define OFF_A   44032    // [2][32][32]    2048
#define OFF_RED 46080    // [2][2048]      4096
#define OFF_US  50176    // [32][36]       1152
#define OFF_PO  51328    // [32][36]       1152
#define OFF_MB  52480
#define SCAN_SMEM_FLOATS 52496

#define CHUNK_BYTES (65536u + 32768u + 4096u + 4096u)

__global__ __launch_bounds__(512, 1)
void scan_kernel(float* __restrict__ outp, float* __restrict__ sFinal) {
    extern __shared__ float sm[];
    const uint32_t smb = smem_u32(sm);
    const uint32_t mbar = smb + OFF_MB*4;

    const int tid = threadIdx.x;
    const int bh = blockIdx.y;
    const int v0 = blockIdx.x * 32;

    float* Ss = sm + OFF_S;
    float* us = sm + OFF_US;
    float* po = sm + OFF_PO;

    const long bhoff  = (long)bh*NCH*CHELEM;
    const long bhoff2 = (long)bh*NCH*(2*CHELEM);
    const long ubase  = ((long)(bh*8 + blockIdx.x))*NCH*CC*32;

    const int slice = tid >> 7;
    const int t128  = tid & 127;
    const int cp2   = t128 >> 3;
    const int vp    = t128 & 7;
    const int c0    = cp2*2;
    const int vv    = vp*4;
    const int c_p2 = tid >> 4;
    const int v_p2 = (tid & 15)*2;
    const int kx3 = (tid >> 3)*4;
    const int vv3 = (tid & 7)*4;

    #pragma unroll
    for (int i = 0; i < 18; i++) Ss[tid + i*512] = 0.0f;

    if (tid == 0) mbar_init(mbar, 1);
    asm volatile("fence.proxy.async.shared::cta;" ::: "memory");
    __syncthreads();
    if (tid == 0) {
        mbar_expect(mbar, CHUNK_BYTES);
        bulkcp(smb + OFF_WQ*4, g_wq + bhoff2, 65536u, mbar);
        bulkcp(smb + OFF_K*4,  g_kn + bhoff,  32768u, mbar);
        bulkcp(smb + OFF_U*4,  g_u + ubase,   4096u,  mbar);
        bulkcp(smb + OFF_A*4,  g_attn + (long)bh*NCH*CC*CC, 4096u, mbar);
    }

    for (int t = 0; t < NCH; t++) {
        mbar_wait(mbar, t & 1);
        __syncthreads();

        const int bsel = t & 1;

        if (tid == 0 && t + 1 < NCH) {
            const int tn = t + 1, nb = tn & 1;
            mbar_expect(mbar, CHUNK_BYTES);
            bulkcp(smb + (OFF_K + nb*8192)*4, g_kn + bhoff + (long)tn*CHELEM, 32768u, mbar);
            bulkcp(smb + (OFF_U + nb*1024)*4, g_u + ubase + (long)tn*CC*32,   4096u,  mbar);
            bulkcp(smb + (OFF_A + nb*1024)*4, g_attn + ((long)bh*NCH + tn)*CC*CC, 4096u, mbar);
        }

        const float* wqb = sm + OFF_WQ;

        // ==== phase 1: u = W.S, o = Q.S ====
        ull ua0=0,ua1=0,ua2=0,ua3=0, oa0=0,oa1=0,oa2=0,oa3=0;
        {
            const int kbase = slice*64;
            #pragma unroll 8
            for (int kk = 0; kk < 64; kk++) {
                const int k = kbase + kk;
                float4 s4 = *(const float4*)&Ss[k*36 + vv];
                ull s01 = pk2(s4.x, s4.y), s23 = pk2(s4.z, s4.w);
                float4 wq = *(const float4*)&wqb[k*64 + cp2*4];
                ull wx = pk2(wq.x, wq.x);
                ffma2(ua0, wx, s01); ffma2(ua1, wx, s23);
                ull wy = pk2(wq.y, wq.y);
                ffma2(ua2, wy, s01); ffma2(ua3, wy, s23);
                ull qx = pk2(wq.z, wq.z);
                ffma2(oa0, qx, s01); ffma2(oa1, qx, s23);
                ull qy = pk2(wq.w, wq.w);
                ffma2(oa2, qy, s01); ffma2(oa3, qy, s23);
            }
        }
        if (slice >= 2) {
            float* red = sm + OFF_RED + (slice-2)*2048;
            float2 a0 = up2(ua0), a1 = up2(ua1), a2 = up2(ua2), a3 = up2(ua3);
            float2 b0 = up2(oa0), b1 = up2(oa1), b2 = up2(oa2), b3 = up2(oa3);
            *(float4*)&red[c0*32 + vv]           = make_float4(a0.x,a0.y,a1.x,a1.y);
            *(float4*)&red[(c0+1)*32 + vv]       = make_float4(a2.x,a2.y,a3.x,a3.y);
            *(float4*)&red[1024 + c0*32 + vv]    = make_float4(b0.x,b0.y,b1.x,b1.y);
            *(float4*)&red[1024 + (c0+1)*32 + vv]= make_float4(b2.x,b2.y,b3.x,b3.y);
        }
        __syncthreads();

        if (tid == 0 && t + 1 < NCH) {
            bulkcp(smb + OFF_WQ*4, g_wq + bhoff2 + (long)(t+1)*(2*CHELEM), 65536u, mbar);
        }

        if (slice < 2) {
            const float* red = sm + OFF_RED + slice*2048;
            float4 ru0 = *(const float4*)&red[c0*32 + vv];
            float4 ru1 = *(const float4*)&red[(c0+1)*32 + vv];
            float4 ro0 = *(const float4*)&red[1024 + c0*32 + vv];
            float4 ro1 = *(const float4*)&red[1024 + (c0+1)*32 + vv];
            fadd2(ua0, pk2(ru0.x,ru0.y)); fadd2(ua1, pk2(ru0.z,ru0.w));
            fadd2(ua2, pk2(ru1.x,ru1.y)); fadd2(ua3, pk2(ru1.z,ru1.w));
            fadd2(oa0, pk2(ro0.x,ro0.y)); fadd2(oa1, pk2(ro0.z,ro0.w));
            fadd2(oa2, pk2(ro1.x,ro1.y)); fadd2(oa3, pk2(ro1.z,ro1.w));
        }
        if (slice == 1) {
            float* red = sm + OFF_RED + 2048;
            float2 a0 = up2(ua0), a1 = up2(ua1), a2 = up2(ua2), a3 = up2(ua3);
            float2 b0 = up2(oa0), b1 = up2(oa1), b2 = up2(oa2), b3 = up2(oa3);
            *(float4*)&red[c0*32 + vv]           = make_float4(a0.x,a0.y,a1.x,a1.y);
            *(float4*)&red[(c0+1)*32 + vv]       = make_float4(a2.x,a2.y,a3.x,a3.y);
            *(float4*)&red[1024 + c0*32 + vv]    = make_float4(b0.x,b0.y,b1.x,b1.y);
            *(float4*)&red[1024 + (c0+1)*32 + vv]= make_float4(b2.x,b2.y,b3.x,b3.y);
        }
        __syncthreads();

        if (slice == 0) {
            const float* red = sm + OFF_RED + 2048;
            float4 ru0 = *(const float4*)&red[c0*32 + vv];
            float4 ru1 = *(const float4*)&red[(c0+1)*32 + vv];
            float4 ro0 = *(const float4*)&red[1024 + c0*32 + vv];
            float4 ro1 = *(const float4*)&red[1024 + (c0+1)*32 + vv];
            fadd2(ua0, pk2(ru0.x,ru0.y)); fadd2(ua1, pk2(ru0.z,ru0.w));
            fadd2(ua2, pk2(ru1.x,ru1.y)); fadd2(ua3, pk2(ru1.z,ru1.w));
            fadd2(oa0, pk2(ro0.x,ro0.y)); fadd2(oa1, pk2(ro0.z,ro0.w));
            fadd2(oa2, pk2(ro1.x,ro1.y)); fadd2(oa3, pk2(ro1.z,ro1.w));

            const float* ub = sm + OFF_U + bsel*1024;
            float4 ur0 = *(const float4*)&ub[c0*32 + vv];
            float4 ur1 = *(const float4*)&ub[(c0+1)*32 + vv];
            float2 u0 = up2(ua0), u1 = up2(ua1), u2 = up2(ua2), u3 = up2(ua3);
            *(float4*)&us[c0*36 + vv] =
                make_float4(ur0.x-u0.x, ur0.y-u0.y, ur0.z-u1.x, ur0.w-u1.y);
            *(float4*)&us[(c0+1)*36 + vv] =
                make_float4(ur1.x-u2.x, ur1.y-u2.y, ur1.z-u3.x, ur1.w-u3.y);
            float2 o0 = up2(oa0), o1 = up2(oa1), o2 = up2(oa2), o3 = up2(oa3);
            *(float4*)&po[c0*36 + vv]     = make_float4(o0.x,o0.y,o1.x,o1.y);
            *(float4*)&po[(c0+1)*36 + vv] = make_float4(o2.x,o2.y,o3.x,o3.y);
        }
        __syncthreads();

        // ==== phase 2: o = po + attn.u (triangular) ====
        {
            const float* ab = sm + OFF_A + bsel*1024;
            float2 pv = *(const float2*)&po[c_p2*36 + v_p2];
            ull oacc = pk2(pv.x, pv.y);
            #pragma unroll 4
            for (int d = 0; d <= c_p2; d++) {
                float2 u2 = *(const float2*)&us[d*36 + v_p2];
                float av = ab[c_p2*32 + d];
                ffma2(oacc, pk2(av, av), pk2(u2.x, u2.y));
            }
            float2 r = up2(oacc);
            *(float2*)(outp + ((long)bh*LSEQ + (long)t*CC + c_p2)*DV + v0 + v_p2) = r;
        }

        // ==== phase 3: S = gm*S + kn^T.u ====
        {
            const float* kb = sm + OFF_K + bsel*8192;
            ull acc0=0,acc1=0,acc2=0,acc3=0,acc4=0,acc5=0,acc6=0,acc7=0;
            #pragma unroll 4
            for (int c = 0; c < 32; c++) {
                float4 kv4 = *(const float4*)&kb[c*256 + kx3];
                float4 u4  = *(const float4*)&us[c*36 + vv3];
                ull u01 = pk2(u4.x, u4.y), u23 = pk2(u4.z, u4.w);
                ull p0 = pk2(kv4.x, kv4.x); ffma2(acc0, p0, u01); ffma2(acc1, p0, u23);
                ull p1 = pk2(kv4.y, kv4.y); ffma2(acc2, p1, u01); ffma2(acc3, p1, u23);
                ull p2 = pk2(kv4.z, kv4.z); ffma2(acc4, p2, u01); ffma2(acc5, p2, u23);
                ull p3 = pk2(kv4.w, kv4.w); ffma2(acc6, p3, u01); ffma2(acc7, p3, u23);
            }
            const float gm = g_gm[bh*NCH + t];
            const ull gmp = pk2(gm, gm);
            const bool last = (t == NCH-1);
            float* sfp = sFinal + (long)bh*DK*DV;
            #pragma unroll
            for (int r = 0; r < 4; r++) {
                const int row = kx3 + r;
                ulonglong2 so = *(const ulonglong2*)&Ss[row*36 + vv3];
                ull n0, n1;
                switch (r) {
                    case 0: n0 = acc0; n1 = acc1; break;
                    case 1: n0 = acc2; n1 = acc3; break;
                    case 2: n0 = acc4; n1 = acc5; break;
                    default: n0 = acc6; n1 = acc7; break;
                }
                ffma2(n0, so.x, gmp);
                ffma2(n1, so.y, gmp);
                ulonglong2 sn; sn.x = n0; sn.y = n1;
                *(ulonglong2*)&Ss[row*36 + vv3] = sn;
                if (last) *(ulonglong2*)&sfp[(long)row*DV + v0 + vv3] = sn;
            }
        }
    }
}

// ================= launch =================
extern "C" void kernel_launch(void* const* d_in, const int* in_sizes, int n_in,
                              void* d_out, int out_size) {
    const float* q     = (const float*)d_in[0];
    const float* k     = (const float*)d_in[1];
    const float* v     = (const float*)d_in[2];
    const float* beta  = (const float*)d_in[3];
    const float* gamma = (const float*)d_in[4];
    float* outp = (float*)d_out;
    float* sfin = outp + (long)BHn*LSEQ*DV;
    cudaFuncSetAttribute(pre_kernel,  cudaFuncAttributeMaxDynamicSharedMemorySize, PRE_SMEM_FLOATS*4);
    cudaFuncSetAttribute(scan_kernel, cudaFuncAttributeMaxDynamicSharedMemorySize, SCAN_SMEM_FLOATS*4);
    (void)in_sizes; (void)n_in; (void)out_size;
    pre_kernel<<<BHn*NCH, 256, PRE_SMEM_FLOATS*4>>>(q, k, v, beta, gamma);
    scan_kernel<<<dim3(8, BHn), 512, SCAN_SMEM_FLOATS*4>>>(outp, sfin);
}

// round 16
// speedup vs baseline: 1.0874x; 1.0184x over previous
#include <cuda_runtime.h>
#include <cuda_bf16.h>
#include <cstdint>

// DeltaNet chunkwise delta-rule linear attention with decay.
// Round 16: scan = round-6 byte-identical (best, 785-789us x6).
// Pre = round-6 body restructured to drop wout[32] (pairwise T-apply, identical
// FLOP/As-read count) + __launch_bounds__(256,3): 71KB smem * 3 = 213.6KB fits,
// regs now fit the 85 cap without spilling -> 3 CTAs/SM, occ 24->36%.

#define BHn 16
#define LSEQ 4096
#define DK 256
#define DV 256
#define CC 32
#define NCH 128
#define CHELEM (CC*DK)

__device__ float g_wq[BHn*NCH*2*CHELEM];   // [bh][ch][k][64] {w2c,w2c+1,q2c,q2c+1}
__device__ float g_kn[BHn*NCH*CHELEM];     // [bh][ch][c][k]
__device__ float g_u [BHn*8*NCH*CC*32];    // [bh][vblk][ch][c][32]
__device__ float g_attn[BHn*NCH*CC*CC];    // [bh][ch][c][d], zero d>c
__device__ float g_gm[BHn*NCH];

typedef unsigned long long ull;
__device__ __forceinline__ void ffma2(ull &d, ull a, ull b) {
    asm("fma.rn.f32x2 %0, %1, %2, %0;" : "+l"(d) : "l"(a), "l"(b));
}
__device__ __forceinline__ void fadd2(ull &d, ull a) {
    asm("add.rn.f32x2 %0, %0, %1;" : "+l"(d) : "l"(a));
}
__device__ __forceinline__ ull pk2(float a, float b) {
    ull r; asm("mov.b64 %0, {%1, %2};" : "=l"(r) : "f"(a), "f"(b)); return r;
}
__device__ __forceinline__ float2 up2(ull p) {
    float2 r; asm("mov.b64 {%0, %1}, %2;" : "=f"(r.x), "=f"(r.y) : "l"(p)); return r;
}
__device__ __forceinline__ uint32_t smem_u32(const void* p) {
    uint32_t a;
    asm("{ .reg .u64 t; cvta.to.shared.u64 t, %1; cvt.u32.u64 %0, t; }" : "=r"(a) : "l"(p));
    return a;
}
__device__ __forceinline__ void bulkcp(uint32_t dst, const void* src, uint32_t bytes, uint32_t mbar) {
    asm volatile("cp.async.bulk.shared::cluster.global.mbarrier::complete_tx::bytes [%0], [%1], %2, [%3];"
                 :: "r"(dst), "l"(src), "r"(bytes), "r"(mbar) : "memory");
}
__device__ __forceinline__ void mbar_init(uint32_t mbar, uint32_t cnt) {
    asm volatile("mbarrier.init.shared.b64 [%0], %1;" :: "r"(mbar), "r"(cnt) : "memory");
}
__device__ __forceinline__ void mbar_expect(uint32_t mbar, uint32_t bytes) {
    asm volatile("mbarrier.arrive.expect_tx.shared.b64 _, [%0], %1;" :: "r"(mbar), "r"(bytes) : "memory");
}
__device__ __forceinline__ void mbar_wait(uint32_t mbar, uint32_t parity) {
    uint32_t done;
    asm volatile("{\n\t.reg .pred p;\n\t"
        "mbarrier.try_wait.parity.acquire.cta.shared::cta.b64 p, [%1], %2;\n\t"
        "selp.b32 %0, 1, 0, p;\n\t}" : "=r"(done) : "r"(mbar), "r"(parity) : "memory");
    if (!done) {
        asm volatile("{\n\t.reg .pred P1;\n\t"
            "WL_%=:\n\t"
            "mbarrier.try_wait.parity.acquire.cta.shared::cta.b64 P1, [%0], %1, 0x989680;\n\t"
            "@P1 bra.uni WD_%=;\n\t"
            "bra.uni WL_%=;\n\t"
            "WD_%=:\n\t}" :: "r"(mbar), "r"(parity) : "memory");
    }
}

// ================= pre (round-6 body, pairwise T-apply, 3 CTAs/SM) =================
#define PRE_SMEM_FLOATS (8320+8320+1056+32+32)

__global__ __launch_bounds__(256, 3)
void pre_kernel(const float* __restrict__ q, const float* __restrict__ k,
                const float* __restrict__ v, const float* __restrict__ beta,
                const float* __restrict__ gamma) {
    extern __shared__ float sm[];
    float* qs = sm; float* ks = sm + 8320; float* As = sm + 16640;
    float* bs = sm + 17696; float* gs = sm + 17728;

    const int tid = threadIdx.x, lane = tid & 31, wid = tid >> 5;
    const int bh = blockIdx.x >> 7, ch = blockIdx.x & 127;
    const long tok0 = (long)bh*LSEQ + (long)ch*CC;
    const float* qg = q + tok0*DK;
    const float* kg = k + tok0*DK;

    #pragma unroll 8
    for (int i = 0; i < 32; i++) {
        qs[i*260+tid] = qg[i*DK+tid];
        ks[i*260+tid] = kg[i*DK+tid];
    }
    if (tid < 32) { bs[tid] = beta[tok0+tid]; gs[tid] = gamma[tok0+tid]; }
    __syncthreads();

    for (int r = wid; r < 32; r += 8) {
        float s = 0.f;
        #pragma unroll
        for (int x = lane; x < 256; x += 32) { float t = qs[r*260+x]; s += t*t; }
        for (int o = 16; o; o >>= 1) s += __shfl_xor_sync(~0u, s, o);
        float inv = rsqrtf(s + 1e-6f);
        #pragma unroll
        for (int x = lane; x < 256; x += 32) qs[r*260+x] *= inv;
        float s2 = 0.f;
        #pragma unroll
        for (int x = lane; x < 256; x += 32) { float t = ks[r*260+x]; s2 += t*t; }
        for (int o = 16; o; o >>= 1) s2 += __shfl_xor_sync(~0u, s2, o);
        float inv2 = rsqrtf(s2 + 1e-6f);
        #pragma unroll
        for (int x = lane; x < 256; x += 32) ks[r*260+x] *= inv2;
    }
    __syncthreads();

    const long cb = ((long)bh*NCH + ch)*CHELEM;
    {
        float* knp = g_kn + cb;
        #pragma unroll 8
        for (int i = 0; i < 32; i++) knp[i*DK+tid] = ks[i*260+tid];
    }

    {
        float* atp = g_attn + ((long)bh*NCH + ch)*CC*CC;
        const int i0 = wid*4;
        float aA[4] = {0,0,0,0}, aQ[4] = {0,0,0,0};
        #pragma unroll 4
        for (int k4 = 0; k4 < 64; k4++) {
            float4 kj = *(float4*)&ks[lane*260 + k4*4];
            #pragma unroll
            for (int r = 0; r < 4; r++) {
                float4 ki = *(float4*)&ks[(i0+r)*260 + k4*4];
                float4 qi = *(float4*)&qs[(i0+r)*260 + k4*4];
                aA[r] += ki.x*kj.x + ki.y*kj.y + ki.z*kj.z + ki.w*kj.w;
                aQ[r] += qi.x*kj.x + qi.y*kj.y + qi.z*kj.z + qi.w*kj.w;
            }
        }
        #pragma unroll
        for (int r = 0; r < 4; r++) {
            if (lane < i0+r) As[(i0+r)*33 + lane] = -bs[i0+r]*aA[r];
            atp[(i0+r)*32 + lane] = (lane <= i0+r) ? aQ[r] : 0.0f;
        }
    }
    __syncthreads();

    if (wid == 0) {
        int col = lane;
        for (int i = 1; i < 32; i++) {
            float inc = 0.f;
            if (col < i) for (int j = col+1; j < i; j++) inc += As[i*33+j]*As[j*33+col];
            __syncwarp();
            if (col < i) As[i*33+col] += inc;
            __syncwarp();
        }
    }
    if (wid == 1) {
        float g2 = gs[lane];
        for (int o = 16; o; o >>= 1) g2 += __shfl_xor_sync(~0u, g2, o);
        if (lane == 0) g_gm[bh*NCH + ch] = g2 * (1.0f/32.0f);
    }
    __syncthreads();

    #pragma unroll
    for (int j = 0; j < 32; j++) ks[j*260 + tid] *= bs[j];

    // fused pairwise T-apply: u = T(beta*v), w = T(beta*kn); only colv[32] lives
    {
        float colv[32];
        const float* vg = v + tok0*DV;
        #pragma unroll
        for (int j = 0; j < 32; j++) colv[j] = vg[j*DV+tid]*bs[j];
        float* up  = g_u + (((long)(bh*8 + (tid>>5))*NCH + ch))*CC*32 + (tid & 31);
        float* wqp = g_wq + ((long)bh*NCH + ch)*(2*CHELEM) + (long)tid*64;
        #pragma unroll
        for (int i = 0; i < 32; i += 2) {
            float accV0 = colv[i],   accK0 = ks[i*260+tid];
            #pragma unroll
            for (int j = 0; j < i; j++) {
                float a = As[i*33+j];
                accV0 += a*colv[j]; accK0 += a*ks[j*260+tid];
            }
            float accV1 = colv[i+1], accK1 = ks[(i+1)*260+tid];
            #pragma unroll
            for (int j = 0; j < i+1; j++) {
                float a = As[(i+1)*33+j];
                accV1 += a*colv[j]; accK1 += a*ks[j*260+tid];
            }
            up[i*32]     = accV0;
            up[(i+1)*32] = accV1;
            *(float4*)&wqp[(i>>1)*4] =
                make_float4(accK0, accK1, qs[i*260+tid], qs[(i+1)*260+tid]);
        }
    }
}

// ================= persistent scan (round-6 version, unchanged) =================
#define OFF_S   0        // [256][36]      9216
#define OFF_WQ  9216     // [256][64]      16384
#define OFF_K   25600    // [2][32][256]   16384
#define OFF_U   41984    // [2][32][32]    2048
#define OFF_A   44032    // [2][32][32]    2048
#define OFF_RED 46080    // [2][2048]      4096
#define OFF_US  50176    // [32][36]       1152
#define OFF_PO  51328    // [32][36]       1152
#define OFF_MB  52480
#define SCAN_SMEM_FLOATS 52496

#define CHUNK_BYTES (65536u + 32768u + 4096u + 4096u)

__global__ __launch_bounds__(512, 1)
void scan_kernel(float* __restrict__ outp, float* __restrict__ sFinal) {
    extern __shared__ float sm[];
    const uint32_t smb = smem_u32(sm);
    const uint32_t mbar = smb + OFF_MB*4;

    const int tid = threadIdx.x;
    const int bh = blockIdx.y;
    const int v0 = blockIdx.x * 32;

    float* Ss = sm + OFF_S;
    float* us = sm + OFF_US;
    float* po = sm + OFF_PO;

    const long bhoff  = (long)bh*NCH*CHELEM;
    const long bhoff2 = (long)bh*NCH*(2*CHELEM);
    const long ubase  = ((long)(bh*8 + blockIdx.x))*NCH*CC*32;

    const int slice = tid >> 7;
    const int t128  = tid & 127;
    const int cp2   = t128 >> 3;
    const int vp    = t128 & 7;
    const int c0    = cp2*2;
    const int vv    = vp*4;
    const int c_p2 = tid >> 4;
    const int v_p2 = (tid & 15)*2;
    const int kx3 = (tid >> 3)*4;
    const int vv3 = (tid & 7)*4;

    #pragma unroll
    for (int i = 0; i < 18; i++) Ss[tid + i*512] = 0.0f;

    if (tid == 0) mbar_init(mbar, 1);
    asm volatile("fence.proxy.async.shared::cta;" ::: "memory");
    __syncthreads();
    if (tid == 0) {
        mbar_expect(mbar, CHUNK_BYTES);
        bulkcp(smb + OFF_WQ*4, g_wq + bhoff2, 65536u, mbar);
        bulkcp(smb + OFF_K*4,  g_kn + bhoff,  32768u, mbar);
        bulkcp(smb + OFF_U*4,  g_u + ubase,   4096u,  mbar);
        bulkcp(smb + OFF_A*4,  g_attn + (long)bh*NCH*CC*CC, 4096u, mbar);
    }

    for (int t = 0; t < NCH; t++) {
        mbar_wait(mbar, t & 1);
        __syncthreads();

        const int bsel = t & 1;

        if (tid == 0 && t + 1 < NCH) {
            const int tn = t + 1, nb = tn & 1;
            mbar_expect(mbar, CHUNK_BYTES);
            bulkcp(smb + (OFF_K + nb*8192)*4, g_kn + bhoff + (long)tn*CHELEM, 32768u, mbar);
            bulkcp(smb + (OFF_U + nb*1024)*4, g_u + ubase + (long)tn*CC*32,   4096u,  mbar);
            bulkcp(smb + (OFF_A + nb*1024)*4, g_attn + ((long)bh*NCH + tn)*CC*CC, 4096u, mbar);
        }

        const float* wqb = sm + OFF_WQ;

        // ==== phase 1: u = W.S, o = Q.S ====
        ull ua0=0,ua1=0,ua2=0,ua3=0, oa0=0,oa1=0,oa2=0,oa3=0;
        {
            const int kbase = slice*64;
            #pragma unroll 8
            for (int kk = 0; kk < 64; kk++) {
                const int k = kbase + kk;
                float4 s4 = *(const float4*)&Ss[k*36 + vv];
                ull s01 = pk2(s4.x, s4.y), s23 = pk2(s4.z, s4.w);
                float4 wq = *(const float4*)&wqb[k*64 + cp2*4];
                ull wx = pk2(wq.x, wq.x);
                ffma2(ua0, wx, s01); ffma2(ua1, wx, s23);
                ull wy = pk2(wq.y, wq.y);
                ffma2(ua2, wy, s01); ffma2(ua3, wy, s23);
                ull qx = pk2(wq.z, wq.z);
                ffma2(oa0, qx, s01); ffma2(oa1, qx, s23);
                ull qy = pk2(wq.w, wq.w);
                ffma2(oa2, qy, s01); ffma2(oa3, qy, s23);
            }
        }
        if (slice >= 2) {
            float* red = sm + OFF_RED + (slice-2)*2048;
            float2 a0 = up2(ua0), a1 = up2(ua1), a2 = up2(ua2), a3 = up2(ua3);
            float2 b0 = up2(oa0), b1 = up2(oa1), b2 = up2(oa2), b3 = up2(oa3);
            *(float4*)&red[c0*32 + vv]           = make_float4(a0.x,a0.y,a1.x,a1.y);
            *(float4*)&red[(c0+1)*32 + vv]       = make_float4(a2.x,a2.y,a3.x,a3.y);
            *(float4*)&red[1024 + c0*32 + vv]    = make_float4(b0.x,b0.y,b1.x,b1.y);
            *(float4*)&red[1024 + (c0+1)*32 + vv]= make_float4(b2.x,b2.y,b3.x,b3.y);
        }
        __syncthreads();

        if (tid == 0 && t + 1 < NCH) {
            bulkcp(smb + OFF_WQ*4, g_wq + bhoff2 + (long)(t+1)*(2*CHELEM), 65536u, mbar);
        }

        if (slice < 2) {
            const float* red = sm + OFF_RED + slice*2048;
            float4 ru0 = *(const float4*)&red[c0*32 + vv];
            float4 ru1 = *(const float4*)&red[(c0+1)*32 + vv];
            float4 ro0 = *(const float4*)&red[1024 + c0*32 + vv];
            float4 ro1 = *(const float4*)&red[1024 + (c0+1)*32 + vv];
            fadd2(ua0, pk2(ru0.x,ru0.y)); fadd2(ua1, pk2(ru0.z,ru0.w));
            fadd2(ua2, pk2(ru1.x,ru1.y)); fadd2(ua3, pk2(ru1.z,ru1.w));
            fadd2(oa0, pk2(ro0.x,ro0.y)); fadd2(oa1, pk2(ro0.z,ro0.w));
            fadd2(oa2, pk2(ro1.x,ro1.y)); fadd2(oa3, pk2(ro1.z,ro1.w));
        }
        if (slice == 1) {
            float* red = sm + OFF_RED + 2048;
            float2 a0 = up2(ua0), a1 = up2(ua1), a2 = up2(ua2), a3 = up2(ua3);
            float2 b0 = up2(oa0), b1 = up2(oa1), b2 = up2(oa2), b3 = up2(oa3);
            *(float4*)&red[c0*32 + vv]           = make_float4(a0.x,a0.y,a1.x,a1.y);
            *(float4*)&red[(c0+1)*32 + vv]       = make_float4(a2.x,a2.y,a3.x,a3.y);
            *(float4*)&red[1024 + c0*32 + vv]    = make_float4(b0.x,b0.y,b1.x,b1.y);
            *(float4*)&red[1024 + (c0+1)*32 + vv]= make_float4(b2.x,b2.y,b3.x,b3.y);
        }
        __syncthreads();

        if (slice == 0) {
            const float* red = sm + OFF_RED + 2048;
            float4 ru0 = *(const float4*)&red[c0*32 + vv];
            float4 ru1 = *(const float4*)&red[(c0+1)*32 + vv];
            float4 ro0 = *(const float4*)&red[1024 + c0*32 + vv];
            float4 ro1 = *(const float4*)&red[1024 + (c0+1)*32 + vv];
            fadd2(ua0, pk2(ru0.x,ru0.y)); fadd2(ua1, pk2(ru0.z,ru0.w));
            fadd2(ua2, pk2(ru1.x,ru1.y)); fadd2(ua3, pk2(ru1.z,ru1.w));
            fadd2(oa0, pk2(ro0.x,ro0.y)); fadd2(oa1, pk2(ro0.z,ro0.w));
            fadd2(oa2, pk2(ro1.x,ro1.y)); fadd2(oa3, pk2(ro1.z,ro1.w));

            const float* ub = sm + OFF_U + bsel*1024;
            float4 ur0 = *(const float4*)&ub[c0*32 + vv];
            float4 ur1 = *(const float4*)&ub[(c0+1)*32 + vv];
            float2 u0 = up2(ua0), u1 = up2(ua1), u2 = up2(ua2), u3 = up2(ua3);
            *(float4*)&us[c0*36 + vv] =
                make_float4(ur0.x-u0.x, ur0.y-u0.y, ur0.z-u1.x, ur0.w-u1.y);
            *(float4*)&us[(c0+1)*36 + vv] =
                make_float4(ur1.x-u2.x, ur1.y-u2.y, ur1.z-u3.x, ur1.w-u3.y);
            float2 o0 = up2(oa0), o1 = up2(oa1), o2 = up2(oa2), o3 = up2(oa3);
            *(float4*)&po[c0*36 + vv]     = make_float4(o0.x,o0.y,o1.x,o1.y);
            *(float4*)&po[(c0+1)*36 + vv] = make_float4(o2.x,o2.y,o3.x,o3.y);
        }
        __syncthreads();

        // ==== phase 2: o = po + attn.u (triangular) ====
        {
            const float* ab = sm + OFF_A + bsel*1024;
            float2 pv = *(const float2*)&po[c_p2*36 + v_p2];
            ull oacc = pk2(pv.x, pv.y);
            #pragma unroll 4
            for (int d = 0; d <= c_p2; d++) {
                float2 u2 = *(const float2*)&us[d*36 + v_p2];
                float av = ab[c_p2*32 + d];
                ffma2(oacc, pk2(av, av), pk2(u2.x, u2.y));
            }
            float2 r = up2(oacc);
            *(float2*)(outp + ((long)bh*LSEQ + (long)t*CC + c_p2)*DV + v0 + v_p2) = r;
        }

        // ==== phase 3: S = gm*S + kn^T.u ====
        {
            const float* kb = sm + OFF_K + bsel*8192;
            ull acc0=0,acc1=0,acc2=0,acc3=0,acc4=0,acc5=0,acc6=0,acc7=0;
            #pragma unroll 4
            for (int c = 0; c < 32; c++) {
                float4 kv4 = *(const float4*)&kb[c*256 + kx3];
                float4 u4  = *(const float4*)&us[c*36 + vv3];
                ull u01 = pk2(u4.x, u4.y), u23 = pk2(u4.z, u4.w);
                ull p0 = pk2(kv4.x, kv4.x); ffma2(acc0, p0, u01); ffma2(acc1, p0, u23);
                ull p1 = pk2(kv4.y, kv4.y); ffma2(acc2, p1, u01); ffma2(acc3, p1, u23);
                ull p2 = pk2(kv4.z, kv4.z); ffma2(acc4, p2, u01); ffma2(acc5, p2, u23);
                ull p3 = pk2(kv4.w, kv4.w); ffma2(acc6, p3, u01); ffma2(acc7, p3, u23);
            }
            const float gm = g_gm[bh*NCH + t];
            const ull gmp = pk2(gm, gm);
            const bool last = (t == NCH-1);
            float* sfp = sFinal + (long)bh*DK*DV;
            #pragma unroll
            for (int r = 0; r < 4; r++) {
                const int row = kx3 + r;
                ulonglong2 so = *(const ulonglong2*)&Ss[row*36 + vv3];
                ull n0, n1;
                switch (r) {
                    case 0: n0 = acc0; n1 = acc1; break;
                    case 1: n0 = acc2; n1 = acc3; break;
                    case 2: n0 = acc4; n1 = acc5; break;
                    default: n0 = acc6; n1 = acc7; break;
                }
                ffma2(n0, so.x, gmp);
                ffma2(n1, so.y, gmp);
                ulonglong2 sn; sn.x = n0; sn.y = n1;
                *(ulonglong2*)&Ss[row*36 + vv3] = sn;
                if (last) *(ulonglong2*)&sfp[(long)row*DV + v0 + vv3] = sn;
            }
        }
    }
}

// ================= launch =================
extern "C" void kernel_launch(void* const* d_in, const int* in_sizes, int n_in,
                              void* d_out, int out_size) {
    const float* q     = (const float*)d_in[0];
    const float* k     = (const float*)d_in[1];
    const float* v     = (const float*)d_in[2];
    const float* beta  = (const float*)d_in[3];
    const float* gamma = (const float*)d_in[4];
    float* outp = (float*)d_out;
    float* sfin = outp + (long)BHn*LSEQ*DV;
    cudaFuncSetAttribute(pre_kernel,  cudaFuncAttributeMaxDynamicSharedMemorySize, PRE_SMEM_FLOATS*4);
    cudaFuncSetAttribute(scan_kernel, cudaFuncAttributeMaxDynamicSharedMemorySize, SCAN_SMEM_FLOATS*4);
    (void)in_sizes; (void)n_in; (void)out_size;
    pre_kernel<<<BHn*NCH, 256, PRE_SMEM_FLOATS*4>>>(q, k, v, beta, gamma);
    scan_kernel<<<dim3(8, BHn), 512, SCAN_SMEM_FLOATS*4>>>(outp, sfin);
}

// round 17
// speedup vs baseline: 1.0986x; 1.0103x over previous
#include <cuda_runtime.h>
#include <cuda_bf16.h>
#include <cstdint>

// DeltaNet chunkwise delta-rule linear attention with decay.
// Round 17: scan = round-6 byte-identical (best, 785-789us x7).
// Pre = round-16 (3 CTAs/SM, pairwise T-apply) + serial-tail overlap:
//   v LDG hoisted before fsub; ks beta-scale done by warps 2-7 during fsub.

#define BHn 16
#define LSEQ 4096
#define DK 256
#define DV 256
#define CC 32
#define NCH 128
#define CHELEM (CC*DK)

__device__ float g_wq[BHn*NCH*2*CHELEM];   // [bh][ch][k][64] {w2c,w2c+1,q2c,q2c+1}
__device__ float g_kn[BHn*NCH*CHELEM];     // [bh][ch][c][k]
__device__ float g_u [BHn*8*NCH*CC*32];    // [bh][vblk][ch][c][32]
__device__ float g_attn[BHn*NCH*CC*CC];    // [bh][ch][c][d], zero d>c
__device__ float g_gm[BHn*NCH];

typedef unsigned long long ull;
__device__ __forceinline__ void ffma2(ull &d, ull a, ull b) {
    asm("fma.rn.f32x2 %0, %1, %2, %0;" : "+l"(d) : "l"(a), "l"(b));
}
__device__ __forceinline__ void fadd2(ull &d, ull a) {
    asm("add.rn.f32x2 %0, %0, %1;" : "+l"(d) : "l"(a));
}
__device__ __forceinline__ ull pk2(float a, float b) {
    ull r; asm("mov.b64 %0, {%1, %2};" : "=l"(r) : "f"(a), "f"(b)); return r;
}
__device__ __forceinline__ float2 up2(ull p) {
    float2 r; asm("mov.b64 {%0, %1}, %2;" : "=f"(r.x), "=f"(r.y) : "l"(p)); return r;
}
__device__ __forceinline__ uint32_t smem_u32(const void* p) {
    uint32_t a;
    asm("{ .reg .u64 t; cvta.to.shared.u64 t, %1; cvt.u32.u64 %0, t; }" : "=r"(a) : "l"(p));
    return a;
}
__device__ __forceinline__ void bulkcp(uint32_t dst, const void* src, uint32_t bytes, uint32_t mbar) {
    asm volatile("cp.async.bulk.shared::cluster.global.mbarrier::complete_tx::bytes [%0], [%1], %2, [%3];"
                 :: "r"(dst), "l"(src), "r"(bytes), "r"(mbar) : "memory");
}
__device__ __forceinline__ void mbar_init(uint32_t mbar, uint32_t cnt) {
    asm volatile("mbarrier.init.shared.b64 [%0], %1;" :: "r"(mbar), "r"(cnt) : "memory");
}
__device__ __forceinline__ void mbar_expect(uint32_t mbar, uint32_t bytes) {
    asm volatile("mbarrier.arrive.expect_tx.shared.b64 _, [%0], %1;" :: "r"(mbar), "r"(bytes) : "memory");
}
__device__ __forceinline__ void mbar_wait(uint32_t mbar, uint32_t parity) {
    uint32_t done;
    asm volatile("{\n\t.reg .pred p;\n\t"
        "mbarrier.try_wait.parity.acquire.cta.shared::cta.b64 p, [%1], %2;\n\t"
        "selp.b32 %0, 1, 0, p;\n\t}" : "=r"(done) : "r"(mbar), "r"(parity) : "memory");
    if (!done) {
        asm volatile("{\n\t.reg .pred P1;\n\t"
            "WL_%=:\n\t"
            "mbarrier.try_wait.parity.acquire.cta.shared::cta.b64 P1, [%0], %1, 0x989680;\n\t"
            "@P1 bra.uni WD_%=;\n\t"
            "bra.uni WL_%=;\n\t"
            "WD_%=:\n\t}" :: "r"(mbar), "r"(parity) : "memory");
    }
}

// ================= pre (3 CTAs/SM + fsub-overlap) =================
#define PRE_SMEM_FLOATS (8320+8320+1056+32+32)

__global__ __launch_bounds__(256, 3)
void pre_kernel(const float* __restrict__ q, const float* __restrict__ k,
                const float* __restrict__ v, const float* __restrict__ beta,
                const float* __restrict__ gamma) {
    extern __shared__ float sm[];
    float* qs = sm; float* ks = sm + 8320; float* As = sm + 16640;
    float* bs = sm + 17696; float* gs = sm + 17728;

    const int tid = threadIdx.x, lane = tid & 31, wid = tid >> 5;
    const int bh = blockIdx.x >> 7, ch = blockIdx.x & 127;
    const long tok0 = (long)bh*LSEQ + (long)ch*CC;
    const float* qg = q + tok0*DK;
    const float* kg = k + tok0*DK;

    #pragma unroll 8
    for (int i = 0; i < 32; i++) {
        qs[i*260+tid] = qg[i*DK+tid];
        ks[i*260+tid] = kg[i*DK+tid];
    }
    if (tid < 32) { bs[tid] = beta[tok0+tid]; gs[tid] = gamma[tok0+tid]; }
    __syncthreads();

    for (int r = wid; r < 32; r += 8) {
        float s = 0.f;
        #pragma unroll
        for (int x = lane; x < 256; x += 32) { float t = qs[r*260+x]; s += t*t; }
        for (int o = 16; o; o >>= 1) s += __shfl_xor_sync(~0u, s, o);
        float inv = rsqrtf(s + 1e-6f);
        #pragma unroll
        for (int x = lane; x < 256; x += 32) qs[r*260+x] *= inv;
        float s2 = 0.f;
        #pragma unroll
        for (int x = lane; x < 256; x += 32) { float t = ks[r*260+x]; s2 += t*t; }
        for (int o = 16; o; o >>= 1) s2 += __shfl_xor_sync(~0u, s2, o);
        float inv2 = rsqrtf(s2 + 1e-6f);
        #pragma unroll
        for (int x = lane; x < 256; x += 32) ks[r*260+x] *= inv2;
    }
    __syncthreads();

    const long cb = ((long)bh*NCH + ch)*CHELEM;
    {
        float* knp = g_kn + cb;
        #pragma unroll 8
        for (int i = 0; i < 32; i++) knp[i*DK+tid] = ks[i*260+tid];
    }

    // ---- Gram: warp = rows i0..i0+3, lane = j ----
    {
        float* atp = g_attn + ((long)bh*NCH + ch)*CC*CC;
        const int i0 = wid*4;
        float aA[4] = {0,0,0,0}, aQ[4] = {0,0,0,0};
        #pragma unroll 4
        for (int k4 = 0; k4 < 64; k4++) {
            float4 kj = *(float4*)&ks[lane*260 + k4*4];
            #pragma unroll
            for (int r = 0; r < 4; r++) {
                float4 ki = *(float4*)&ks[(i0+r)*260 + k4*4];
                float4 qi = *(float4*)&qs[(i0+r)*260 + k4*4];
                aA[r] += ki.x*kj.x + ki.y*kj.y + ki.z*kj.z + ki.w*kj.w;
                aQ[r] += qi.x*kj.x + qi.y*kj.y + qi.z*kj.z + qi.w*kj.w;
            }
        }
        #pragma unroll
        for (int r = 0; r < 4; r++) {
            if (lane < i0+r) As[(i0+r)*33 + lane] = -bs[i0+r]*aA[r];
            atp[(i0+r)*32 + lane] = (lane <= i0+r) ? aQ[r] : 0.0f;
        }
    }
    __syncthreads();

    // ---- hoisted v load (unscaled) — LDGs fly during fsub ----
    float colv[32];
    {
        const float* vg = v + tok0*DV;
        #pragma unroll
        for (int j = 0; j < 32; j++) colv[j] = vg[j*DV+tid];
    }

    // ---- overlapped section: warp0 = fsub, warp1 = gamma, warps 2-7 = ks*beta ----
    if (wid == 0) {
        int col = lane;
        for (int i = 1; i < 32; i++) {
            float inc = 0.f;
            if (col < i) for (int j = col+1; j < i; j++) inc += As[i*33+j]*As[j*33+col];
            __syncwarp();
            if (col < i) As[i*33+col] += inc;
            __syncwarp();
        }
    } else if (wid == 1) {
        float g2 = gs[lane];
        for (int o = 16; o; o >>= 1) g2 += __shfl_xor_sync(~0u, g2, o);
        if (lane == 0) g_gm[bh*NCH + ch] = g2 * (1.0f/32.0f);
    } else {
        // 192 threads scale 32x256 elements of ks (disjoint from As/gs)
        for (int idx = tid - 64; idx < 8192; idx += 192) {
            int row = idx >> 8, col = idx & 255;
            ks[row*260 + col] *= bs[row];
        }
    }
    __syncthreads();

    // ---- fused pairwise T-apply: u = T(beta*v), w = T(beta*kn) ----
    {
        #pragma unroll
        for (int j = 0; j < 32; j++) colv[j] *= bs[j];
        float* up  = g_u + (((long)(bh*8 + (tid>>5))*NCH + ch))*CC*32 + (tid & 31);
        float* wqp = g_wq + ((long)bh*NCH + ch)*(2*CHELEM) + (long)tid*64;
        #pragma unroll
        for (int i = 0; i < 32; i += 2) {
            float accV0 = colv[i],   accK0 = ks[i*260+tid];
            #pragma unroll
            for (int j = 0; j < i; j++) {
                float a = As[i*33+j];
                accV0 += a*colv[j]; accK0 += a*ks[j*260+tid];
            }
            float accV1 = colv[i+1], accK1 = ks[(i+1)*260+tid];
            #pragma unroll
            for (int j = 0; j < i+1; j++) {
                float a = As[(i+1)*33+j];
                accV1 += a*colv[j]; accK1 += a*ks[j*260+tid];
            }
            up[i*32]     = accV0;
            up[(i+1)*32] = accV1;
            *(float4*)&wqp[(i>>1)*4] =
                make_float4(accK0, accK1, qs[i*260+tid], qs[(i+1)*260+tid]);
        }
    }
}

// ================= persistent scan (round-6 version, unchanged) =================
#define OFF_S   0        // [256][36]      9216
#define OFF_WQ  9216     // [256][64]      16384
#define OFF_K   25600    // [2][32][256]   16384
#define OFF_U   41984    // [2][32][32]    2048
#define OFF_A   44032    // [2][32][32]    2048
#define OFF_RED 46080    // [2][2048]      4096
#define OFF_US  50176    // [32][36]       1152
#define OFF_PO  51328    // [32][36]       1152
#define OFF_MB  52480
#define SCAN_SMEM_FLOATS 52496

#define CHUNK_BYTES (65536u + 32768u + 4096u + 4096u)

__global__ __launch_bounds__(512, 1)
void scan_kernel(float* __restrict__ outp, float* __restrict__ sFinal) {
    extern __shared__ float sm[];
    const uint32_t smb = smem_u32(sm);
    const uint32_t mbar = smb + OFF_MB*4;

    const int tid = threadIdx.x;
    const int bh = blockIdx.y;
    const int v0 = blockIdx.x * 32;

    float* Ss = sm + OFF_S;
    float* us = sm + OFF_US;
    float* po = sm + OFF_PO;

    const long bhoff  = (long)bh*NCH*CHELEM;
    const long bhoff2 = (long)bh*NCH*(2*CHELEM);
    const long ubase  = ((long)(bh*8 + blockIdx.x))*NCH*CC*32;

    const int slice = tid >> 7;
    const int t128  = tid & 127;
    const int cp2   = t128 >> 3;
    const int vp    = t128 & 7;
    const int c0    = cp2*2;
    const int vv    = vp*4;
    const int c_p2 = tid >> 4;
    const int v_p2 = (tid & 15)*2;
    const int kx3 = (tid >> 3)*4;
    const int vv3 = (tid & 7)*4;

    #pragma unroll
    for (int i = 0; i < 18; i++) Ss[tid + i*512] = 0.0f;

    if (tid == 0) mbar_init(mbar, 1);
    asm volatile("fence.proxy.async.shared::cta;" ::: "memory");
    __syncthreads();
    if (tid == 0) {
        mbar_expect(mbar, CHUNK_BYTES);
        bulkcp(smb + OFF_WQ*4, g_wq + bhoff2, 65536u, mbar);
        bulkcp(smb + OFF_K*4,  g_kn + bhoff,  32768u, mbar);
        bulkcp(smb + OFF_U*4,  g_u + ubase,   4096u,  mbar);
        bulkcp(smb + OFF_A*4,  g_attn + (long)bh*NCH*CC*CC, 4096u, mbar);
    }

    for (int t = 0; t < NCH; t++) {
        mbar_wait(mbar, t & 1);
        __syncthreads();

        const int bsel = t & 1;

        if (tid == 0 && t + 1 < NCH) {
            const int tn = t + 1, nb = tn & 1;
            mbar_expect(mbar, CHUNK_BYTES);
            bulkcp(smb + (OFF_K + nb*8192)*4, g_kn + bhoff + (long)tn*CHELEM, 32768u, mbar);
            bulkcp(smb + (OFF_U + nb*1024)*4, g_u + ubase + (long)tn*CC*32,   4096u,  mbar);
            bulkcp(smb + (OFF_A + nb*1024)*4, g_attn + ((long)bh*NCH + tn)*CC*CC, 4096u, mbar);
        }

        const float* wqb = sm + OFF_WQ;

        // ==== phase 1: u = W.S, o = Q.S ====
        ull ua0=0,ua1=0,ua2=0,ua3=0, oa0=0,oa1=0,oa2=0,oa3=0;
        {
            const int kbase = slice*64;
            #pragma unroll 8
            for (int kk = 0; kk < 64; kk++) {
                const int k = kbase + kk;
                float4 s4 = *(const float4*)&Ss[k*36 + vv];
                ull s01 = pk2(s4.x, s4.y), s23 = pk2(s4.z, s4.w);
                float4 wq = *(const float4*)&wqb[k*64 + cp2*4];
                ull wx = pk2(wq.x, wq.x);
                ffma2(ua0, wx, s01); ffma2(ua1, wx, s23);
                ull wy = pk2(wq.y, wq.y);
                ffma2(ua2, wy, s01); ffma2(ua3, wy, s23);
                ull qx = pk2(wq.z, wq.z);
                ffma2(oa0, qx, s01); ffma2(oa1, qx, s23);
                ull qy = pk2(wq.w, wq.w);
                ffma2(oa2, qy, s01); ffma2(oa3, qy, s23);
            }
        }
        if (slice >= 2) {
            float* red = sm + OFF_RED + (slice-2)*2048;
            float2 a0 = up2(ua0), a1 = up2(ua1), a2 = up2(ua2), a3 = up2(ua3);
            float2 b0 = up2(oa0), b1 = up2(oa1), b2 = up2(oa2), b3 = up2(oa3);
            *(float4*)&red[c0*32 + vv]           = make_float4(a0.x,a0.y,a1.x,a1.y);
            *(float4*)&red[(c0+1)*32 + vv]       = make_float4(a2.x,a2.y,a3.x,a3.y);
            *(float4*)&red[1024 + c0*32 + vv]    = make_float4(b0.x,b0.y,b1.x,b1.y);
            *(float4*)&red[1024 + (c0+1)*32 + vv]= make_float4(b2.x,b2.y,b3.x,b3.y);
        }
        __syncthreads();

        if (tid == 0 && t + 1 < NCH) {
            bulkcp(smb + OFF_WQ*4, g_wq + bhoff2 + (long)(t+1)*(2*CHELEM), 65536u, mbar);
        }

        if (slice < 2) {
            const float* red = sm + OFF_RED + slice*2048;
            float4 ru0 = *(const float4*)&red[c0*32 + vv];
            float4 ru1 = *(const float4*)&red[(c0+1)*32 + vv];
            float4 ro0 = *(const float4*)&red[1024 + c0*32 + vv];
            float4 ro1 = *(const float4*)&red[1024 + (c0+1)*32 + vv];
            fadd2(ua0, pk2(ru0.x,ru0.y)); fadd2(ua1, pk2(ru0.z,ru0.w));
            fadd2(ua2, pk2(ru1.x,ru1.y)); fadd2(ua3, pk2(ru1.z,ru1.w));
            fadd2(oa0, pk2(ro0.x,ro0.y)); fadd2(oa1, pk2(ro0.z,ro0.w));
            fadd2(oa2, pk2(ro1.x,ro1.y)); fadd2(oa3, pk2(ro1.z,ro1.w));
        }
        if (slice == 1) {
            float* red = sm + OFF_RED + 2048;
            float2 a0 = up2(ua0), a1 = up2(ua1), a2 = up2(ua2), a3 = up2(ua3);
            float2 b0 = up2(oa0), b1 = up2(oa1), b2 = up2(oa2), b3 = up2(oa3);
            *(float4*)&red[c0*32 + vv]           = make_float4(a0.x,a0.y,a1.x,a1.y);
            *(float4*)&red[(c0+1)*32 + vv]       = make_float4(a2.x,a2.y,a3.x,a3.y);
            *(float4*)&red[1024 + c0*32 + vv]    = make_float4(b0.x,b0.y,b1.x,b1.y);
            *(float4*)&red[1024 + (c0+1)*32 + vv]= make_float4(b2.x,b2.y,b3.x,b3.y);
        }
        __syncthreads();

        if (slice == 0) {
            const float* red = sm + OFF_RED + 2048;
            float4 ru0 = *(const float4*)&red[c0*32 + vv];
            float4 ru1 = *(const float4*)&red[(c0+1)*32 + vv];
            float4 ro0 = *(const float4*)&red[1024 + c0*32 + vv];
            float4 ro1 = *(const float4*)&red[1024 + (c0+1)*32 + vv];
            fadd2(ua0, pk2(ru0.x,ru0.y)); fadd2(ua1, pk2(ru0.z,ru0.w));
            fadd2(ua2, pk2(ru1.x,ru1.y)); fadd2(ua3, pk2(ru1.z,ru1.w));
            fadd2(oa0, pk2(ro0.x,ro0.y)); fadd2(oa1, pk2(ro0.z,ro0.w));
            fadd2(oa2, pk2(ro1.x,ro1.y)); fadd2(oa3, pk2(ro1.z,ro1.w));

            const float* ub = sm + OFF_U + bsel*1024;
            float4 ur0 = *(const float4*)&ub[c0*32 + vv];
            float4 ur1 = *(const float4*)&ub[(c0+1)*32 + vv];
            float2 u0 = up2(ua0), u1 = up2(ua1), u2 = up2(ua2), u3 = up2(ua3);
            *(float4*)&us[c0*36 + vv] =
                make_float4(ur0.x-u0.x, ur0.y-u0.y, ur0.z-u1.x, ur0.w-u1.y);
            *(float4*)&us[(c0+1)*36 + vv] =
                make_float4(ur1.x-u2.x, ur1.y-u2.y, ur1.z-u3.x, ur1.w-u3.y);
            float2 o0 = up2(oa0), o1 = up2(oa1), o2 = up2(oa2), o3 = up2(oa3);
            *(float4*)&po[c0*36 + vv]     = make_float4(o0.x,o0.y,o1.x,o1.y);
            *(float4*)&po[(c0+1)*36 + vv] = make_float4(o2.x,o2.y,o3.x,o3.y);
        }
        __syncthreads();

        // ==== phase 2: o = po + attn.u (triangular) ====
        {
            const float* ab = sm + OFF_A + bsel*1024;
            float2 pv = *(const float2*)&po[c_p2*36 + v_p2];
            ull oacc = pk2(pv.x, pv.y);
            #pragma unroll 4
            for (int d = 0; d <= c_p2; d++) {
                float2 u2 = *(const float2*)&us[d*36 + v_p2];
                float av = ab[c_p2*32 + d];
                ffma2(oacc, pk2(av, av), pk2(u2.x, u2.y));
            }
            float2 r = up2(oacc);
            *(float2*)(outp + ((long)bh*LSEQ + (long)t*CC + c_p2)*DV + v0 + v_p2) = r;
        }

        // ==== phase 3: S = gm*S + kn^T.u ====
        {
            const float* kb = sm + OFF_K + bsel*8192;
            ull acc0=0,acc1=0,acc2=0,acc3=0,acc4=0,acc5=0,acc6=0,acc7=0;
            #pragma unroll 4
            for (int c = 0; c < 32; c++) {
                float4 kv4 = *(const float4*)&kb[c*256 + kx3];
                float4 u4  = *(const float4*)&us[c*36 + vv3];
                ull u01 = pk2(u4.x, u4.y), u23 = pk2(u4.z, u4.w);
                ull p0 = pk2(kv4.x, kv4.x); ffma2(acc0, p0, u01); ffma2(acc1, p0, u23);
                ull p1 = pk2(kv4.y, kv4.y); ffma2(acc2, p1, u01); ffma2(acc3, p1, u23);
                ull p2 = pk2(kv4.z, kv4.z); ffma2(acc4, p2, u01); ffma2(acc5, p2, u23);
                ull p3 = pk2(kv4.w, kv4.w); ffma2(acc6, p3, u01); ffma2(acc7, p3, u23);
            }
            const float gm = g_gm[bh*NCH + t];
            const ull gmp = pk2(gm, gm);
            const bool last = (t == NCH-1);
            float* sfp = sFinal + (long)bh*DK*DV;
            #pragma unroll
            for (int r = 0; r < 4; r++) {
                const int row = kx3 + r;
                ulonglong2 so = *(const ulonglong2*)&Ss[row*36 + vv3];
                ull n0, n1;
                switch (r) {
                    case 0: n0 = acc0; n1 = acc1; break;
                    case 1: n0 = acc2; n1 = acc3; break;
                    case 2: n0 = acc4; n1 = acc5; break;
                    default: n0 = acc6; n1 = acc7; break;
                }
                ffma2(n0, so.x, gmp);
                ffma2(n1, so.y, gmp);
                ulonglong2 sn; sn.x = n0; sn.y = n1;
                *(ulonglong2*)&Ss[row*36 + vv3] = sn;
                if (last) *(ulonglong2*)&sfp[(long)row*DV + v0 + vv3] = sn;
            }
        }
    }
}

// ================= launch =================
extern "C" void kernel_launch(void* const* d_in, const int* in_sizes, int n_in,
                              void* d_out, int out_size) {
    const float* q     = (const float*)d_in[0];
    const float* k     = (const float*)d_in[1];
    const float* v     = (const float*)d_in[2];
    const float* beta  = (const float*)d_in[3];
    const float* gamma = (const float*)d_in[4];
    float* outp = (float*)d_out;
    float* sfin = outp + (long)BHn*LSEQ*DV;
    cudaFuncSetAttribute(pre_kernel,  cudaFuncAttributeMaxDynamicSharedMemorySize, PRE_SMEM_FLOATS*4);
    cudaFuncSetAttribute(scan_kernel, cudaFuncAttributeMaxDynamicSharedMemorySize, SCAN_SMEM_FLOATS*4);
    (void)in_sizes; (void)n_in; (void)out_size;
    pre_kernel<<<BHn*NCH, 256, PRE_SMEM_FLOATS*4>>>(q, k, v, beta, gamma);
    scan_kernel<<<dim3(8, BHn), 512, SCAN_SMEM_FLOATS*4>>>(outp, sfin);
}